// round 15
// baseline (speedup 1.0000x reference)
#include <cuda_runtime.h>
#include <math.h>

#define HEADS   16
#define HD      64
#define DIMM    1024
#define QKVS    3072
#define TXT     226
#define IMGL    1536
#define SEQ     1762
#define NCPT    8
#define FRAMES  4
#define PATCHES 384
#define FFD     4096
#define TDIM    512
#define RMAIN   3524
#define RTOT    3540
#define CKEYS   1544

#define OE     3145728
#define OC     3608576
#define OSEL   3624960
#define OIMAP  3637248
#define OCMAP  3649536
#define OXMAP  3661824

// ---------------- device scratch ----------------
__device__ float g_s1[2*6*DIMM];
__device__ float g_s2[2*6*DIMM];
__device__ float g_x   [RTOT*DIMM];
__device__ float g_qkv [(size_t)RTOT*QKVS];
__device__ float g_attn[RTOT*DIMM];
__device__ float g_res [RTOT*DIMM];
__device__ float g_ffh [(size_t)RTOT*FFD];
__device__ float g_part[(size_t)4*RTOT*DIMM];
__device__ float g_wqkv[(size_t)DIMM*QKVS];
__device__ float g_wo  [(size_t)DIMM*DIMM];
__device__ float g_w1  [(size_t)DIMM*FFD];
__device__ float g_w2  [(size_t)FFD*DIMM];
__device__ float g_cs[(size_t)2*HEADS*NCPT*CKEYS];
__device__ float g_hscore[HEADS];
__device__ int   g_selhead[4];
__device__ int   g_selvis[HEADS*NCPT*FRAMES];
__device__ float g_imap[HEADS*NCPT*IMGL];

__device__ __forceinline__ unsigned f2tf32(float x) {
    unsigned u;
    asm("cvt.rna.tf32.f32 %0, %1;" : "=r"(u) : "f"(x));
    return u;
}
__device__ __forceinline__ float rndf(float x) { return __uint_as_float(f2tf32(x)); }

// ---------------- reductions ----------------
__device__ __forceinline__ float blockReduceSum(float v, float* red) {
    int lane = threadIdx.x & 31, w = threadIdx.x >> 5;
    #pragma unroll
    for (int o = 16; o; o >>= 1) v += __shfl_xor_sync(0xffffffffu, v, o);
    if (lane == 0) red[w] = v;
    __syncthreads();
    int nw = (blockDim.x + 31) >> 5;
    float r = (threadIdx.x < nw) ? red[threadIdx.x] : 0.f;
    if (w == 0) {
        #pragma unroll
        for (int o = 16; o; o >>= 1) r += __shfl_xor_sync(0xffffffffu, r, o);
        if (lane == 0) red[0] = r;
    }
    __syncthreads();
    r = red[0];
    __syncthreads();
    return r;
}

__device__ __forceinline__ float blockReduceMax(float v, float* red) {
    int lane = threadIdx.x & 31, w = threadIdx.x >> 5;
    #pragma unroll
    for (int o = 16; o; o >>= 1) v = fmaxf(v, __shfl_xor_sync(0xffffffffu, v, o));
    if (lane == 0) red[w] = v;
    __syncthreads();
    int nw = (blockDim.x + 31) >> 5;
    float r = (threadIdx.x < nw) ? red[threadIdx.x] : -1e30f;
    if (w == 0) {
        #pragma unroll
        for (int o = 16; o; o >>= 1) r = fmaxf(r, __shfl_xor_sync(0xffffffffu, r, o));
        if (lane == 0) red[0] = r;
    }
    __syncthreads();
    r = red[0];
    __syncthreads();
    return r;
}

// ---------------- weight prep: round to tf32 once ----------------
__global__ void k_prep(const float* __restrict__ wq, const float* __restrict__ wk,
                       const float* __restrict__ wv, const float* __restrict__ wo,
                       const float* __restrict__ w1, const float* __restrict__ w2)
{
    int i = blockIdx.x*256 + threadIdx.x;
    if (i < DIMM*DIMM) {
        int k = i >> 10, n = i & 1023;
        g_wqkv[(size_t)k*QKVS + n]        = rndf(wq[i]);
        g_wqkv[(size_t)k*QKVS + 1024 + n] = rndf(wk[i]);
        g_wqkv[(size_t)k*QKVS + 2048 + n] = rndf(wv[i]);
        g_wo[i] = rndf(wo[i]);
    }
    size_t stride = (size_t)gridDim.x*256;
    for (size_t j = i; j < (size_t)DIMM*FFD; j += stride) {
        g_w1[j] = rndf(w1[j]);
        g_w2[j] = rndf(w2[j]);
    }
}

// ---------------- modulation vectors: s = silu(temb) @ W + b ----------------
__global__ void k_mod(const float* __restrict__ temb,
                      const float* __restrict__ w1, const float* __restrict__ b1,
                      const float* __restrict__ w2, const float* __restrict__ b2)
{
    int j   = blockIdx.x * 256 + threadIdx.x;
    int b   = blockIdx.y;
    int set = blockIdx.z;
    const float* W  = set ? w2 : w1;
    const float* Bb = set ? b2 : b1;
    float* out      = set ? g_s2 : g_s1;
    __shared__ float st[TDIM];
    for (int i = threadIdx.x; i < TDIM; i += 256) {
        float x = temb[b*TDIM + i];
        st[i] = x / (1.f + __expf(-x));
    }
    __syncthreads();
    float acc = Bb[j];
    for (int k = 0; k < TDIM; k++)
        acc += st[k] * W[(size_t)k*6*DIMM + j];
    out[b*6*DIMM + j] = acc;
}

// ---------------- LayerNorm + adaLN modulation -> g_x (tf32-rounded, GEMM-only) ----------------
__global__ void k_ln_mod(const float* __restrict__ e_in, const float* __restrict__ h_in,
                         const float* __restrict__ c_in, int use_res, int use_s2,
                         const float* __restrict__ lnw, const float* __restrict__ lnb)
{
    int r = blockIdx.x, tid = threadIdx.x;
    int b, sh_c, sc_c;
    const float* src;
    if (r < RMAIN) {
        b = r / SEQ; int s = r - b*SEQ;
        if (use_res) src = g_res + (size_t)r*DIMM;
        else src = (s < TXT) ? e_in + ((size_t)b*TXT + s)*DIMM
                             : h_in + ((size_t)b*IMGL + (s - TXT))*DIMM;
        if (s < TXT) { sh_c = 3; sc_c = 4; } else { sh_c = 0; sc_c = 1; }
    } else {
        int qq = r - RMAIN; b = qq / NCPT;
        src = use_res ? g_res + (size_t)r*DIMM : c_in + (size_t)qq*DIMM;
        sh_c = 3; sc_c = 4;
    }
    __shared__ float xs[DIMM];
    __shared__ float red[32];
    float ls = 0.f, lq = 0.f;
    #pragma unroll
    for (int i = 0; i < 4; i++) {
        float x = src[tid + i*256];
        xs[tid + i*256] = x;
        ls += x; lq += x*x;
    }
    float ts = blockReduceSum(ls, red);
    float tq = blockReduceSum(lq, red);
    float mu   = ts * (1.f/DIMM);
    float var  = tq * (1.f/DIMM) - mu*mu;
    float rstd = rsqrtf(var + 1e-5f);
    const float* S  = (use_s2 ? g_s2 : g_s1) + b*6*DIMM;
    #pragma unroll
    for (int i = 0; i < 4; i++) {
        int j = tid + i*256;
        float y = (xs[j] - mu)*rstd*lnw[j] + lnb[j];
        y = y * (1.f + S[sc_c*DIMM + j]) + S[sh_c*DIMM + j];
        g_x[(size_t)r*DIMM + j] = rndf(y);
    }
}

// ---------------- TF32 GEMM: 128x128, cp.async 3-stage + ldmatrix ----------------
// ACT: 0 none, 1 tanh-gelu. z-split via zA/zB/zC offsets.
#define ASTR 36
#define BSTRG 136
#define ABYTES (128*ASTR*4)
#define BBYTES (32*BSTRG*4)
#define STAGE_BYTES (ABYTES + BBYTES)
#define SMEM_GEMM (3*STAGE_BYTES)

__device__ __forceinline__ void cp16(unsigned sm, const float* gp, unsigned sz) {
    asm volatile("cp.async.ca.shared.global [%0], [%1], 16, %2;\n" :: "r"(sm), "l"(gp), "r"(sz));
}
__device__ __forceinline__ uint4 ldm4(unsigned addr) {
    uint4 r;
    asm volatile("ldmatrix.sync.aligned.m8n8.x4.shared.b16 {%0,%1,%2,%3}, [%4];\n"
        : "=r"(r.x), "=r"(r.y), "=r"(r.z), "=r"(r.w) : "r"(addr));
    return r;
}

template<int ACT, int ROUND>
__global__ void __launch_bounds__(256, 2)
mma_gemm(const float* __restrict__ A, const float* __restrict__ B,
         const float* __restrict__ bias, float* __restrict__ C,
         int M, int N, int K, int lda, int ldb, int ldc,
         long zA, long zB, long zC)
{
    extern __shared__ __align__(16) char smem_raw[];
    unsigned smem_base = (unsigned)__cvta_generic_to_shared(smem_raw);

    int z = blockIdx.z;
    A += (long)z*zA; B += (long)z*zB; C += (long)z*zC;

    int m0 = blockIdx.y*128, n0 = blockIdx.x*128;
    int tid = threadIdx.x, lane = tid & 31, w = tid >> 5;
    int wm = w & 1, wn = w >> 1;
    int g = lane >> 2, c = lane & 3;

    int arow = tid >> 1;
    int acol = (tid & 1) * 16;
    int gmrow = m0 + arow;
    const float* agp = A + (long)(gmrow < M ? gmrow : 0)*lda + acol;
    unsigned apred = (gmrow < M) ? 16u : 0u;
    unsigned asm0 = smem_base + (unsigned)(arow*ASTR + acol)*4u;
    int bkr = tid >> 3;
    int bcol = (tid & 7) * 16;
    const float* bgp = B + (long)bkr*ldb + n0 + bcol;
    unsigned bsm0 = smem_base + (unsigned)ABYTES + (unsigned)(bkr*BSTRG + bcol)*4u;

    unsigned a_lane = (unsigned)(((((lane>>3)&1)*8 + (lane&7))*ASTR + (lane>>4)*4)*4);

    float acc[4][4][4];
    #pragma unroll
    for (int i = 0; i < 4; i++)
        #pragma unroll
        for (int j = 0; j < 4; j++)
            #pragma unroll
            for (int k = 0; k < 4; k++) acc[i][j][k] = 0.f;

    int ntile = K >> 5;

#define ISSUE(KT, BUF)                                                         \
    {                                                                          \
        unsigned so = (unsigned)(BUF)*STAGE_BYTES;                             \
        const float* ag = agp + (KT)*32;                                       \
        _Pragma("unroll")                                                      \
        for (int j = 0; j < 4; j++) cp16(asm0 + so + j*16, ag + j*4, apred);   \
        const float* bg = bgp + (long)(KT)*32*ldb;                             \
        _Pragma("unroll")                                                      \
        for (int j = 0; j < 4; j++) cp16(bsm0 + so + j*16, bg + j*4, 16u);     \
        asm volatile("cp.async.commit_group;\n");                              \
    }

    ISSUE(0, 0);
    ISSUE(1, 1);

    for (int kt = 0; kt < ntile; kt++) {
        int buf = kt % 3;
        asm volatile("cp.async.wait_group 1;\n" ::: "memory");
        __syncthreads();

        unsigned Abase = smem_base + (unsigned)buf*STAGE_BYTES + a_lane
                       + (unsigned)(wm*64*ASTR)*4u;
        const unsigned* Bp = (const unsigned*)(smem_raw + buf*STAGE_BYTES + ABYTES);

        #pragma unroll
        for (int ks = 0; ks < 4; ks++) {
            uint4 a[4];
            #pragma unroll
            for (int mt = 0; mt < 4; mt++)
                a[mt] = ldm4(Abase + (unsigned)((mt*16*ASTR + ks*8)*4));
            int kc = ks*8 + c;
            unsigned b[4][2];
            #pragma unroll
            for (int nt = 0; nt < 4; nt++) {
                int nb = wn*32 + nt*8 + g;
                b[nt][0] = Bp[kc*BSTRG + nb];
                b[nt][1] = Bp[(kc+4)*BSTRG + nb];
            }
            #pragma unroll
            for (int mt = 0; mt < 4; mt++)
                #pragma unroll
                for (int nt = 0; nt < 4; nt++) {
                    asm volatile(
                        "mma.sync.aligned.m16n8k8.row.col.f32.tf32.tf32.f32 "
                        "{%0,%1,%2,%3}, {%4,%5,%6,%7}, {%8,%9}, {%0,%1,%2,%3};\n"
                        : "+f"(acc[mt][nt][0]), "+f"(acc[mt][nt][1]),
                          "+f"(acc[mt][nt][2]), "+f"(acc[mt][nt][3])
                        : "r"(a[mt].x), "r"(a[mt].y), "r"(a[mt].z), "r"(a[mt].w),
                          "r"(b[nt][0]), "r"(b[nt][1]));
                }
        }
        if (kt + 2 < ntile) { ISSUE(kt + 2, (kt + 2) % 3); }
        else asm volatile("cp.async.commit_group;\n");
    }
#undef ISSUE

    #pragma unroll
    for (int mt = 0; mt < 4; mt++) {
        #pragma unroll
        for (int half = 0; half < 2; half++) {
            int rr = m0 + wm*64 + mt*16 + g + half*8;
            if (rr >= M) continue;
            #pragma unroll
            for (int nt = 0; nt < 4; nt++) {
                int c0 = n0 + wn*32 + nt*8 + 2*c;
                if (c0 >= N) continue;
                float v0 = acc[mt][nt][half*2 + 0];
                float v1 = acc[mt][nt][half*2 + 1];
                if (bias) { v0 += bias[c0]; v1 += bias[c0+1]; }
                if (ACT == 1) {
                    float u = v0;
                    v0 = 0.5f*u*(1.f + tanhf(0.79788456080286535588f*(u + 0.044715f*u*u*u)));
                    u = v1;
                    v1 = 0.5f*u*(1.f + tanhf(0.79788456080286535588f*(u + 0.044715f*u*u*u)));
                }
                if (ROUND) { v0 = rndf(v0); v1 = rndf(v1); }
                *(float2*)&C[(long)rr*ldc + c0] = make_float2(v0, v1);
            }
        }
    }
}

// ---------------- split-K Wo reduce + resid1 -> g_res ----------------
__global__ void k_wored(const float* __restrict__ e_in, const float* __restrict__ h_in,
                        const float* __restrict__ c_in, const float* __restrict__ bias)
{
    int r = blockIdx.x, t = threadIdx.x;
    const float* src; int b, gcol;
    if (r < RMAIN) {
        b = r / SEQ; int s = r - b*SEQ;
        if (s < TXT) { src = e_in + ((size_t)b*TXT + s)*DIMM; gcol = 5; }
        else         { src = h_in + ((size_t)b*IMGL + (s - TXT))*DIMM; gcol = 2; }
    } else {
        int qq = r - RMAIN; b = qq / NCPT;
        src = c_in + (size_t)qq*DIMM; gcol = 5;
    }
    const float* g = g_s1 + b*6*DIMM + gcol*DIMM;
    #pragma unroll
    for (int i = 0; i < 4; i++) {
        int j = t + i*256;
        float v = g_part[(size_t)r*DIMM + j]
                + g_part[(size_t)(RTOT + r)*DIMM + j] + bias[j];
        g_res[(size_t)r*DIMM + j] = src[j] + g[j]*v;
    }
}

// ---------------- split-K FF2 reduce + resid2 -> final outputs ----------------
__global__ void k_ff2red(float* __restrict__ out, const float* __restrict__ bias)
{
    int r = blockIdx.x, t = threadIdx.x;
    float* dst; int b, gcol;
    if (r < RMAIN) {
        b = r / SEQ; int s = r - b*SEQ;
        if (s < TXT) { dst = out + OE + ((size_t)b*TXT + s)*DIMM; gcol = 5; }
        else         { dst = out + ((size_t)b*IMGL + (s - TXT))*DIMM; gcol = 2; }
    } else {
        int qq = r - RMAIN; b = qq / NCPT;
        dst = out + OC + (size_t)qq*DIMM; gcol = 5;
    }
    const float* g = g_s2 + b*6*DIMM + gcol*DIMM;
    #pragma unroll
    for (int i = 0; i < 4; i++) {
        int j = t + i*256;
        float v = (g_part[(size_t)r*DIMM + j]
                +  g_part[(size_t)(RTOT + r)*DIMM + j])
                + (g_part[(size_t)(2*RTOT + r)*DIMM + j]
                +  g_part[(size_t)(3*RTOT + r)*DIMM + j]) + bias[j];
        dst[j] = g_res[(size_t)r*DIMM + j] + g[j]*v;
    }
}

// ---------------- fused flash attention over g_qkv (stride 3072) ----------------
#define KSTR 68
#define VSTR 65
#define PSTR 68
#define FLASH_SMEM ((64*KSTR + 64*VSTR + 8*16*PSTR)*4)

__global__ void __launch_bounds__(256, 2)
k_flash(const float* __restrict__ qkv, float* __restrict__ og)
{
    extern __shared__ __align__(16) unsigned fsm[];
    unsigned* Ks = fsm;
    unsigned* Vs = Ks + 64*KSTR;
    unsigned* Ps = Vs + 64*VSTR;

    const float* qg = qkv;
    const float* kg = qkv + 1024;
    const float* vg = qkv + 2048;

    int b = blockIdx.y >> 4, h = blockIdx.y & 15;
    int tid = threadIdx.x, lane = tid & 31, w = tid >> 5;
    int g = lane >> 2, c = lane & 3;
    int r0 = blockIdx.x*128 + w*16 + g;
    int r1 = r0 + 8;
    bool v0 = r0 < SEQ, v1 = r1 < SEQ;

    unsigned qf[8][4];
    {
        const float* q0 = qg + (size_t)(b*SEQ + (v0 ? r0 : 0))*QKVS + h*HD;
        const float* q1 = qg + (size_t)(b*SEQ + (v1 ? r1 : 0))*QKVS + h*HD;
        #pragma unroll
        for (int ks = 0; ks < 8; ks++) {
            qf[ks][0] = v0 ? f2tf32(q0[ks*8 + c])     : 0u;
            qf[ks][1] = v1 ? f2tf32(q1[ks*8 + c])     : 0u;
            qf[ks][2] = v0 ? f2tf32(q0[ks*8 + c + 4]) : 0u;
            qf[ks][3] = v1 ? f2tf32(q1[ks*8 + c + 4]) : 0u;
        }
    }

    float mr0 = -1e30f, mr1 = -1e30f;
    float lr0 = 0.f, lr1 = 0.f;
    float O[8][4];
    #pragma unroll
    for (int i = 0; i < 8; i++)
        #pragma unroll
        for (int j = 0; j < 4; j++) O[i][j] = 0.f;

    int kk = tid & 63;
    int dg = (tid >> 6) * 16;
    unsigned* Pw = Ps + w*16*PSTR;

    const int NTILES = (SEQ + 63) / 64;
    for (int t = 0; t < NTILES; t++) {
        __syncthreads();
        {
            int j = t*64 + kk;
            bool jv = j < SEQ;
            const float* kp = kg + (size_t)(b*SEQ + (jv ? j : 0))*QKVS + h*HD + dg;
            const float* vp = vg + (size_t)(b*SEQ + (jv ? j : 0))*QKVS + h*HD + dg;
            #pragma unroll
            for (int i = 0; i < 4; i++) {
                float4 k4 = jv ? *(const float4*)(kp + i*4) : make_float4(0,0,0,0);
                float4 w4 = jv ? *(const float4*)(vp + i*4) : make_float4(0,0,0,0);
                int d = dg + i*4;
                Ks[(d+0)*KSTR + kk] = f2tf32(k4.x);
                Ks[(d+1)*KSTR + kk] = f2tf32(k4.y);
                Ks[(d+2)*KSTR + kk] = f2tf32(k4.z);
                Ks[(d+3)*KSTR + kk] = f2tf32(k4.w);
                Vs[kk*VSTR + d+0] = f2tf32(w4.x);
                Vs[kk*VSTR + d+1] = f2tf32(w4.y);
                Vs[kk*VSTR + d+2] = f2tf32(w4.z);
                Vs[kk*VSTR + d+3] = f2tf32(w4.w);
            }
        }
        __syncthreads();

        float s[8][4];
        #pragma unroll
        for (int i = 0; i < 8; i++)
            #pragma unroll
            for (int j = 0; j < 4; j++) s[i][j] = 0.f;
        #pragma unroll
        for (int ks = 0; ks < 8; ks++) {
            int kc = ks*8 + c;
            #pragma unroll
            for (int nt = 0; nt < 8; nt++) {
                unsigned b0 = Ks[kc*KSTR + nt*8 + g];
                unsigned b1 = Ks[(kc+4)*KSTR + nt*8 + g];
                asm volatile(
                    "mma.sync.aligned.m16n8k8.row.col.f32.tf32.tf32.f32 "
                    "{%0,%1,%2,%3}, {%4,%5,%6,%7}, {%8,%9}, {%0,%1,%2,%3};\n"
                    : "+f"(s[nt][0]), "+f"(s[nt][1]), "+f"(s[nt][2]), "+f"(s[nt][3])
                    : "r"(qf[ks][0]), "r"(qf[ks][1]), "r"(qf[ks][2]), "r"(qf[ks][3]),
                      "r"(b0), "r"(b1));
            }
        }

        int jb = t*64 + 2*c;
        #pragma unroll
        for (int nt = 0; nt < 8; nt++) {
            int j0 = jb + nt*8, j1 = j0 + 1;
            s[nt][0] = (j0 < SEQ) ? s[nt][0]*0.125f : -1e30f;
            s[nt][1] = (j1 < SEQ) ? s[nt][1]*0.125f : -1e30f;
            s[nt][2] = (j0 < SEQ) ? s[nt][2]*0.125f : -1e30f;
            s[nt][3] = (j1 < SEQ) ? s[nt][3]*0.125f : -1e30f;
        }
        float mx0 = -1e30f, mx1 = -1e30f;
        #pragma unroll
        for (int nt = 0; nt < 8; nt++) {
            mx0 = fmaxf(mx0, fmaxf(s[nt][0], s[nt][1]));
            mx1 = fmaxf(mx1, fmaxf(s[nt][2], s[nt][3]));
        }
        mx0 = fmaxf(mx0, __shfl_xor_sync(0xffffffffu, mx0, 1));
        mx0 = fmaxf(mx0, __shfl_xor_sync(0xffffffffu, mx0, 2));
        mx1 = fmaxf(mx1, __shfl_xor_sync(0xffffffffu, mx1, 1));
        mx1 = fmaxf(mx1, __shfl_xor_sync(0xffffffffu, mx1, 2));
        float nm0 = fmaxf(mr0, mx0), nm1 = fmaxf(mr1, mx1);
        float sc0 = __expf(mr0 - nm0), sc1 = __expf(mr1 - nm1);
        float rs0 = 0.f, rs1 = 0.f;
        #pragma unroll
        for (int nt = 0; nt < 8; nt++) {
            float p0 = __expf(s[nt][0] - nm0);
            float p1 = __expf(s[nt][1] - nm0);
            float p2 = __expf(s[nt][2] - nm1);
            float p3 = __expf(s[nt][3] - nm1);
            rs0 += p0 + p1; rs1 += p2 + p3;
            int col = nt*8 + 2*c;
            *(uint2*)&Pw[g*PSTR + col]     = make_uint2(f2tf32(p0), f2tf32(p1));
            *(uint2*)&Pw[(g+8)*PSTR + col] = make_uint2(f2tf32(p2), f2tf32(p3));
        }
        rs0 += __shfl_xor_sync(0xffffffffu, rs0, 1);
        rs0 += __shfl_xor_sync(0xffffffffu, rs0, 2);
        rs1 += __shfl_xor_sync(0xffffffffu, rs1, 1);
        rs1 += __shfl_xor_sync(0xffffffffu, rs1, 2);
        lr0 = lr0*sc0 + rs0;
        lr1 = lr1*sc1 + rs1;
        mr0 = nm0; mr1 = nm1;
        #pragma unroll
        for (int nt = 0; nt < 8; nt++) {
            O[nt][0] *= sc0; O[nt][1] *= sc0;
            O[nt][2] *= sc1; O[nt][3] *= sc1;
        }
        __syncwarp();

        #pragma unroll
        for (int ks = 0; ks < 8; ks++) {
            int kc = ks*8 + c;
            unsigned a0 = Pw[g*PSTR + kc];
            unsigned a1 = Pw[(g+8)*PSTR + kc];
            unsigned a2 = Pw[g*PSTR + kc + 4];
            unsigned a3 = Pw[(g+8)*PSTR + kc + 4];
            #pragma unroll
            for (int nt = 0; nt < 8; nt++) {
                unsigned b0 = Vs[kc*VSTR + nt*8 + g];
                unsigned b1 = Vs[(kc+4)*VSTR + nt*8 + g];
                asm volatile(
                    "mma.sync.aligned.m16n8k8.row.col.f32.tf32.tf32.f32 "
                    "{%0,%1,%2,%3}, {%4,%5,%6,%7}, {%8,%9}, {%0,%1,%2,%3};\n"
                    : "+f"(O[nt][0]), "+f"(O[nt][1]), "+f"(O[nt][2]), "+f"(O[nt][3])
                    : "r"(a0), "r"(a1), "r"(a2), "r"(a3),
                      "r"(b0), "r"(b1));
            }
        }
        __syncwarp();
    }

    float i0 = 1.f/lr0, i1 = 1.f/lr1;
    if (v0) {
        float* op = og + (size_t)(b*SEQ + r0)*DIMM + h*HD;
        #pragma unroll
        for (int nt = 0; nt < 8; nt++)
            *(float2*)&op[nt*8 + 2*c] = make_float2(O[nt][0]*i0, O[nt][1]*i0);
    }
    if (v1) {
        float* op = og + (size_t)(b*SEQ + r1)*DIMM + h*HD;
        #pragma unroll
        for (int nt = 0; nt < 8; nt++)
            *(float2*)&op[nt*8 + 2*c] = make_float2(O[nt][2]*i1, O[nt][3]*i1);
    }
}

// ---------------- per-head LN (+RoPE) on q/k within g_qkv (full fp32 out) ----------------
__global__ void k_headln(float* __restrict__ x, const float* __restrict__ nw,
                         const float* __restrict__ nb,
                         const float* __restrict__ rc, const float* __restrict__ rs)
{
    int w = blockIdx.x * 8 + (threadIdx.x >> 5);
    if (w >= RTOT*HEADS) return;
    int lane = threadIdx.x & 31;
    int r = w >> 4, h = w & 15;
    float* p = x + (size_t)r*QKVS + h*HD;
    float v0 = p[lane], v1 = p[lane + 32];
    float s = v0 + v1;
    #pragma unroll
    for (int o = 16; o; o >>= 1) s += __shfl_xor_sync(0xffffffffu, s, o);
    float mu = s * (1.f/64.f);
    float d0 = v0 - mu, d1 = v1 - mu;
    float qv = d0*d0 + d1*d1;
    #pragma unroll
    for (int o = 16; o; o >>= 1) qv += __shfl_xor_sync(0xffffffffu, qv, o);
    float rstd = rsqrtf(qv*(1.f/64.f) + 1e-6f);
    float y0 = d0*rstd*nw[lane]    + nb[lane];
    float y1 = d1*rstd*nw[lane+32] + nb[lane+32];
    if (r < RMAIN) {
        int sidx = r % SEQ;
        if (sidx >= TXT) {
            int pos = sidx - TXT;
            const float* c  = rc + (size_t)pos*HD;
            const float* sn = rs + (size_t)pos*HD;
            float p0 = __shfl_xor_sync(0xffffffffu, y0, 1);
            float p1 = __shfl_xor_sync(0xffffffffu, y1, 1);
            float r0 = (lane & 1) ? p0 : -p0;
            float r1 = (lane & 1) ? p1 : -p1;
            y0 = y0*c[lane]    + r0*sn[lane];
            y1 = y1*c[lane+32] + r1*sn[lane+32];
        }
    }
    p[lane] = y0; p[lane+32] = y1;
}

// ---------------- concept attention: scores+softmax per (b,h,c) ----------------
__global__ void k_cscore(const float* __restrict__ qkv)
{
    int bid = blockIdx.x;
    int b = bid >> 7, h = (bid >> 3) & 15, c = bid & 7;
    int t = threadIdx.x;
    __shared__ float qs[HD];
    __shared__ float red[32];
    const float* qrow = qkv + (size_t)(RMAIN + b*NCPT + c)*QKVS + h*HD;
    if (t < HD) qs[t] = qrow[t];
    __syncthreads();
    float v[7];
    float m = -1e30f;
    #pragma unroll
    for (int i = 0; i < 7; i++) {
        int j = t + i*256;
        if (j < CKEYS) {
            const float* krow = (j < NCPT)
                ? qkv + (size_t)(RMAIN + b*NCPT + j)*QKVS + 1024 + h*HD
                : qkv + (size_t)(b*SEQ + TXT + (j - NCPT))*QKVS + 1024 + h*HD;
            float a = 0.f;
            for (int d = 0; d < HD; d++) a += qs[d]*krow[d];
            v[i] = a*0.125f;
        } else v[i] = -1e30f;
        m = fmaxf(m, v[i]);
    }
    m = blockReduceMax(m, red);
    float s = 0.f;
    #pragma unroll
    for (int i = 0; i < 7; i++) {
        int j = t + i*256;
        v[i] = (j < CKEYS) ? __expf(v[i]-m) : 0.f;
        s += v[i];
    }
    s = blockReduceSum(s, red);
    float inv = 1.f/s;
    float* out = g_cs + ((size_t)(b*HEADS + h)*NCPT + c)*CKEYS;
    #pragma unroll
    for (int i = 0; i < 7; i++) {
        int j = t + i*256;
        if (j < CKEYS) out[j] = v[i]*inv;
    }
}

__global__ void k_cpv(const float* __restrict__ qkv)
{
    int bid = blockIdx.x; int b = bid >> 7, h = (bid >> 3) & 15, c = bid & 7;
    int t = threadIdx.x;
    int d  = t & 63;
    int jg = t >> 6;
    const float* p = g_cs + ((size_t)(b*HEADS + h)*NCPT + c)*CKEYS;
    float acc = 0.f;
    for (int j = jg; j < CKEYS; j += 4) {
        const float* vrow = (j < NCPT)
            ? qkv + (size_t)(RMAIN + b*NCPT + j)*QKVS + 2048 + h*HD
            : qkv + (size_t)(b*SEQ + TXT + (j - NCPT))*QKVS + 2048 + h*HD;
        acc += p[j]*vrow[d];
    }
    __shared__ float part[4][64];
    part[jg][d] = acc;
    __syncthreads();
    if (t < 64)
        g_attn[(size_t)(RMAIN + b*NCPT + c)*DIMM + h*HD + t] =
            part[0][t] + part[1][t] + part[2][t] + part[3][t];
}

// ---------------- head score (batch 1), top-k ----------------
__global__ void k_headscore()
{
    int h = blockIdx.x, t = threadIdx.x;
    float s1 = 0.f, s2 = 0.f;
    for (int p = t; p < IMGL; p += 256) {
        const float* row = g_attn + (size_t)(SEQ + TXT + p)*DIMM + h*HD;
        float m = 0.f;
        for (int d = 0; d < HD; d++) m += row[d];
        m *= (1.f/64.f);
        s1 += m; s2 += m*m;
    }
    __shared__ float red[32];
    s1 = blockReduceSum(s1, red);
    s2 = blockReduceSum(s2, red);
    if (t == 0) {
        float mu = s1/IMGL;
        g_hscore[h] = sqrtf(fmaxf(s2/IMGL - mu*mu, 0.f));
    }
}

__global__ void k_topk()
{
    if (threadIdx.x) return;
    bool used[HEADS] = {};
    for (int i = 0; i < 4; i++) {
        int bi = -1; float bv = -1e30f;
        for (int hh = 0; hh < HEADS; hh++)
            if (!used[hh] && g_hscore[hh] > bv) { bv = g_hscore[hh]; bi = hh; }
        used[bi] = true; g_selhead[i] = bi;
    }
}

// ---------------- sim argmax over patches per (h, concept, frame) ----------------
__global__ void k_simargmax(const float* __restrict__ qkv)
{
    int h = blockIdx.x, tc = blockIdx.y, f = blockIdx.z;
    int t = threadIdx.x;
    __shared__ float ks[HD];
    if (t < HD) ks[t] = qkv[(size_t)(RMAIN + NCPT + tc)*QKVS + 1024 + h*HD + t];
    __syncthreads();
    float bv = -1e30f; int bi = 0;
    #pragma unroll
    for (int i = 0; i < 3; i++) {
        int p = t + i*128;
        const float* qrow = qkv + (size_t)(SEQ + TXT + f*PATCHES + p)*QKVS + h*HD;
        float a = 0.f;
        for (int d = 0; d < HD; d++) a += qrow[d]*ks[d];
        if (a > bv) { bv = a; bi = p; }
    }
    __shared__ float sv[128]; __shared__ int si[128];
    sv[t] = bv; si[t] = bi;
    __syncthreads();
    for (int o = 64; o; o >>= 1) {
        if (t < o) {
            if (sv[t+o] > sv[t] || (sv[t+o] == sv[t] && si[t+o] < si[t])) {
                sv[t] = sv[t+o]; si[t] = si[t+o];
            }
        }
        __syncthreads();
    }
    if (t == 0) g_selvis[(h*NCPT + tc)*FRAMES + f] = si[0];
}

// ---------------- imap per (h, f) ----------------
__global__ void k_imap()
{
    int h = blockIdx.x, f = blockIdx.y;
    int t = threadIdx.x;
    __shared__ float sel[NCPT][HD];
    for (int idx = t; idx < NCPT*HD; idx += 384) {
        int tc = idx >> 6, d = idx & 63;
        int sp = g_selvis[(h*NCPT + tc)*FRAMES + f];
        sel[tc][d] = g_attn[(size_t)(SEQ + TXT + f*PATCHES + sp)*DIMM + h*HD + d];
    }
    __syncthreads();
    const float* row = g_attn + (size_t)(SEQ + TXT + f*PATCHES + t)*DIMM + h*HD;
    float a[NCPT] = {};
    for (int d = 0; d < HD; d++) {
        float x = row[d];
        #pragma unroll
        for (int tc = 0; tc < NCPT; tc++) a[tc] += sel[tc][d]*x;
    }
    float mu = 0.f;
    #pragma unroll
    for (int tc = 0; tc < NCPT; tc++) mu += a[tc];
    mu *= (1.f/8.f);
    float var = 0.f;
    #pragma unroll
    for (int tc = 0; tc < NCPT; tc++) { float d_ = a[tc]-mu; var += d_*d_; }
    float sd = sqrtf(var*(1.f/7.f)) + 1e-6f;
    #pragma unroll
    for (int tc = 0; tc < NCPT; tc++)
        g_imap[((size_t)(h*NCPT + tc))*IMGL + f*PATCHES + t] = (a[tc]-mu)/sd;
}

__global__ void k_selfinal(float* __restrict__ out)
{
    int idx = blockIdx.x*256 + threadIdx.x;
    if (idx >= NCPT*IMGL) return;
    int tc = idx / IMGL, p = idx % IMGL;
    float ssum = 0.f;
    for (int i = 0; i < 4; i++)
        ssum += g_imap[((size_t)(g_selhead[i]*NCPT + tc))*IMGL + p];
    out[OSEL + idx] = ssum*0.25f;
    float tot = 0.f;
    for (int h = 0; h < HEADS; h++)
        tot += g_imap[((size_t)(h*NCPT + tc))*IMGL + p];
    out[OIMAP + idx] = tot;
}

// ---------------- cross/concept maps ----------------
__global__ void k_dotmaps(const float* __restrict__ A, const float* __restrict__ Brows,
                          int lda, int ldb, float* __restrict__ out, float scale)
{
    int w = blockIdx.x*8 + (threadIdx.x >> 5);
    if (w >= NCPT*IMGL) return;
    int lane = threadIdx.x & 31;
    int c = w / IMGL, p = w % IMGL;
    const float* a = A     + (size_t)(SEQ + TXT + p)*lda;
    const float* b = Brows + (size_t)(RMAIN + NCPT + c)*ldb;
    float s = 0.f;
    for (int i = lane; i < DIMM; i += 32) s += a[i]*b[i];
    #pragma unroll
    for (int o = 16; o; o >>= 1) s += __shfl_xor_sync(0xffffffffu, s, o);
    if (lane == 0) out[c*IMGL + p] = s*scale;
}

// ---------------- host launcher ----------------
static float* symf(const void* symbol) {
    void* p = nullptr;
    cudaGetSymbolAddress(&p, symbol);
    return (float*)p;
}

extern "C" void kernel_launch(void* const* d_in, const int* in_sizes, int n_in,
                              void* d_out, int out_size)
{
    const float* h_in  = (const float*)d_in[0];
    const float* e_in  = (const float*)d_in[1];
    const float* c_in  = (const float*)d_in[2];
    const float* temb  = (const float*)d_in[3];
    const float* ropec = (const float*)d_in[4];
    const float* ropes = (const float*)d_in[5];
    const float* n1w   = (const float*)d_in[6];
    const float* n1b   = (const float*)d_in[7];
    const float* ln1w  = (const float*)d_in[8];
    const float* ln1b  = (const float*)d_in[9];
    const float* n2w   = (const float*)d_in[10];
    const float* n2b   = (const float*)d_in[11];
    const float* ln2w  = (const float*)d_in[12];
    const float* ln2b  = (const float*)d_in[13];
    const float* wq    = (const float*)d_in[14];
    const float* wk    = (const float*)d_in[15];
    const float* wv    = (const float*)d_in[16];
    const float* nqw   = (const float*)d_in[17];
    const float* nqb   = (const float*)d_in[18];
    const float* nkw   = (const float*)d_in[19];
    const float* nkb   = (const float*)d_in[20];
    const float* wo    = (const float*)d_in[21];
    const float* bo    = (const float*)d_in[22];
    const float* ffw1  = (const float*)d_in[23];
    const float* ffb1  = (const float*)d_in[24];
    const float* ffw2  = (const float*)d_in[25];
    const float* ffb2  = (const float*)d_in[26];
    float* out = (float*)d_out;

    float* px    = symf(g_x);
    float* pqkv  = symf(g_qkv);
    float* pattn = symf(g_attn);
    float* pffh  = symf(g_ffh);
    float* ppart = symf(g_part);
    float* pwqkv = symf(g_wqkv);
    float* pwo   = symf(g_wo);
    float* pw1   = symf(g_w1);
    float* pw2   = symf(g_w2);

    cudaFuncSetAttribute(mma_gemm<0,0>, cudaFuncAttributeMaxDynamicSharedMemorySize, SMEM_GEMM);
    cudaFuncSetAttribute(mma_gemm<1,1>, cudaFuncAttributeMaxDynamicSharedMemorySize, SMEM_GEMM);
    cudaFuncSetAttribute(k_flash, cudaFuncAttributeMaxDynamicSharedMemorySize, FLASH_SMEM);

    static cudaStream_t s1 = nullptr, s2 = nullptr;
    static cudaEvent_t e_prep, e_qkv, e_hq, e_hk, e_flash, e_cpv, e_sim, e_end1, e_end2;
    if (!s1) {
        cudaStreamCreateWithFlags(&s1, cudaStreamNonBlocking);
        cudaStreamCreateWithFlags(&s2, cudaStreamNonBlocking);
        cudaEventCreateWithFlags(&e_prep,  cudaEventDisableTiming);
        cudaEventCreateWithFlags(&e_qkv,   cudaEventDisableTiming);
        cudaEventCreateWithFlags(&e_hq,    cudaEventDisableTiming);
        cudaEventCreateWithFlags(&e_hk,    cudaEventDisableTiming);
        cudaEventCreateWithFlags(&e_flash, cudaEventDisableTiming);
        cudaEventCreateWithFlags(&e_cpv,   cudaEventDisableTiming);
        cudaEventCreateWithFlags(&e_sim,   cudaEventDisableTiming);
        cudaEventCreateWithFlags(&e_end1,  cudaEventDisableTiming);
        cudaEventCreateWithFlags(&e_end2,  cudaEventDisableTiming);
    }
    cudaStream_t s0 = 0;

    // fork side streams from s0
    cudaEventRecord(e_qkv, s0);
    cudaStreamWaitEvent(s1, e_qkv, 0);
    cudaStreamWaitEvent(s2, e_qkv, 0);
    k_prep<<<4096, 256, 0, s1>>>(wq, wk, wv, wo, ffw1, ffw2);
    cudaEventRecord(e_prep, s1);

    k_mod<<<dim3(24,2,2), 256, 0, s0>>>(temb, n1w, n1b, n2w, n2b);
    k_ln_mod<<<RTOT, 256, 0, s0>>>(e_in, h_in, c_in, 0, 0, ln1w, ln1b);

    cudaStreamWaitEvent(s0, e_prep, 0);
    mma_gemm<0,0><<<dim3(24,28),256,SMEM_GEMM,s0>>>(px, pwqkv, nullptr, pqkv,
                                                    RTOT, QKVS, DIMM, DIMM, QKVS, QKVS,
                                                    0, 0, 0);
    cudaEventRecord(e_qkv, s0);

    cudaStreamWaitEvent(s1, e_qkv, 0);
    k_headln<<<7080, 256, 0, s0>>>(pqkv,        nqw, nqb, ropec, ropes);
    cudaEventRecord(e_hq, s0);
    k_headln<<<7080, 256, 0, s1>>>(pqkv + 1024, nkw, nkb, ropec, ropes);
    cudaEventRecord(e_hk, s1);

    cudaStreamWaitEvent(s0, e_hk, 0);
    k_flash<<<dim3(14, 32), 256, FLASH_SMEM, s0>>>(pqkv, pattn);
    cudaEventRecord(e_flash, s0);

    cudaStreamWaitEvent(s1, e_hq, 0);
    k_cscore<<<256, 256, 0, s1>>>(pqkv);
    k_cpv<<<256, 256, 0, s1>>>(pqkv);
    cudaEventRecord(e_cpv, s1);

    cudaStreamWaitEvent(s2, e_hq, 0);
    cudaStreamWaitEvent(s2, e_hk, 0);
    k_simargmax<<<dim3(HEADS, NCPT, FRAMES), 128, 0, s2>>>(pqkv);
    cudaEventRecord(e_sim, s2);
    k_dotmaps<<<1536, 256, 0, s2>>>(pqkv, pqkv + 1024, QKVS, QKVS, out + OXMAP, 1.f/16.f);
    cudaStreamWaitEvent(s2, e_flash, 0);
    cudaStreamWaitEvent(s2, e_cpv, 0);
    k_dotmaps<<<1536, 256, 0, s2>>>(pattn, pattn, DIMM, DIMM, out + OCMAP, 1.f);
    cudaEventRecord(e_end2, s2);

    cudaStreamWaitEvent(s1, e_flash, 0);
    k_headscore<<<HEADS, 256, 0, s1>>>();
    k_topk<<<1, 32, 0, s1>>>();
    cudaStreamWaitEvent(s1, e_sim, 0);
    k_imap<<<dim3(HEADS, FRAMES), PATCHES, 0, s1>>>();
    k_selfinal<<<48, 256, 0, s1>>>(out);
    cudaEventRecord(e_end1, s1);

    // Wo projection: split-K=2 partials, then reduce + resid1
    cudaStreamWaitEvent(s0, e_cpv, 0);
    mma_gemm<0,0><<<dim3(8,28,2),256,SMEM_GEMM,s0>>>(pattn, pwo, nullptr, ppart,
                                                     RTOT, DIMM, 512, DIMM, DIMM, DIMM,
                                                     512L, 512L*DIMM, (long)RTOT*DIMM);
    k_wored<<<RTOT, 256, 0, s0>>>(e_in, h_in, c_in, bo);

    // LN phase 2, FF1, split-K=4 FF2 partials, reduce + resid2
    k_ln_mod<<<RTOT, 256, 0, s0>>>(e_in, h_in, c_in, 1, 1, ln2w, ln2b);
    mma_gemm<1,1><<<dim3(32,28),256,SMEM_GEMM,s0>>>(px, pw1, ffb1, pffh,
                                                    RTOT, FFD, DIMM, DIMM, FFD, FFD,
                                                    0, 0, 0);
    mma_gemm<0,0><<<dim3(8,28,4),256,SMEM_GEMM,s0>>>(pffh, pw2, nullptr, ppart,
                                                     RTOT, DIMM, 1024, FFD, DIMM, DIMM,
                                                     1024L, 1024L*DIMM, (long)RTOT*DIMM);
    k_ff2red<<<RTOT, 256, 0, s0>>>(out, ffb2);

    cudaStreamWaitEvent(s0, e_end1, 0);
    cudaStreamWaitEvent(s0, e_end2, 0);
}

// round 16
// speedup vs baseline: 1.0068x; 1.0068x over previous
#include <cuda_runtime.h>
#include <math.h>

#define HEADS   16
#define HD      64
#define DIMM    1024
#define QKVS    3072
#define TXT     226
#define IMGL    1536
#define SEQ     1762
#define NCPT    8
#define FRAMES  4
#define PATCHES 384
#define FFD     4096
#define TDIM    512
#define RMAIN   3524
#define RTOT    3540
#define CKEYS   1544

#define OE     3145728
#define OC     3608576
#define OSEL   3624960
#define OIMAP  3637248
#define OCMAP  3649536
#define OXMAP  3661824

// ---------------- device scratch ----------------
__device__ float g_s1[2*6*DIMM];
__device__ float g_s2[2*6*DIMM];
__device__ float g_x   [RTOT*DIMM];
__device__ float g_qkv [(size_t)RTOT*QKVS];
__device__ float g_attn[RTOT*DIMM];
__device__ float g_res [RTOT*DIMM];
__device__ float g_ffh [(size_t)RTOT*FFD];
__device__ float g_part[(size_t)4*RTOT*DIMM];
__device__ float g_wqkv[(size_t)DIMM*QKVS];
__device__ float g_wo  [(size_t)DIMM*DIMM];
__device__ float g_w1  [(size_t)DIMM*FFD];
__device__ float g_w2  [(size_t)FFD*DIMM];
__device__ float g_cs[(size_t)2*HEADS*NCPT*CKEYS];
__device__ float g_hscore[HEADS];
__device__ int   g_selhead[4];
__device__ int   g_selvis[HEADS*NCPT*FRAMES];
__device__ float g_imap[HEADS*NCPT*IMGL];

__device__ __forceinline__ unsigned f2tf32(float x) {
    unsigned u;
    asm("cvt.rna.tf32.f32 %0, %1;" : "=r"(u) : "f"(x));
    return u;
}
__device__ __forceinline__ float rndf(float x) { return __uint_as_float(f2tf32(x)); }

// ---------------- reductions ----------------
__device__ __forceinline__ float blockReduceSum(float v, float* red) {
    int lane = threadIdx.x & 31, w = threadIdx.x >> 5;
    #pragma unroll
    for (int o = 16; o; o >>= 1) v += __shfl_xor_sync(0xffffffffu, v, o);
    if (lane == 0) red[w] = v;
    __syncthreads();
    int nw = (blockDim.x + 31) >> 5;
    float r = (threadIdx.x < nw) ? red[threadIdx.x] : 0.f;
    if (w == 0) {
        #pragma unroll
        for (int o = 16; o; o >>= 1) r += __shfl_xor_sync(0xffffffffu, r, o);
        if (lane == 0) red[0] = r;
    }
    __syncthreads();
    r = red[0];
    __syncthreads();
    return r;
}

__device__ __forceinline__ float blockReduceMax(float v, float* red) {
    int lane = threadIdx.x & 31, w = threadIdx.x >> 5;
    #pragma unroll
    for (int o = 16; o; o >>= 1) v = fmaxf(v, __shfl_xor_sync(0xffffffffu, v, o));
    if (lane == 0) red[w] = v;
    __syncthreads();
    int nw = (blockDim.x + 31) >> 5;
    float r = (threadIdx.x < nw) ? red[threadIdx.x] : -1e30f;
    if (w == 0) {
        #pragma unroll
        for (int o = 16; o; o >>= 1) r = fmaxf(r, __shfl_xor_sync(0xffffffffu, r, o));
        if (lane == 0) red[0] = r;
    }
    __syncthreads();
    r = red[0];
    __syncthreads();
    return r;
}

// ---------------- weight prep: round to tf32 once ----------------
__global__ void k_prep(const float* __restrict__ wq, const float* __restrict__ wk,
                       const float* __restrict__ wv, const float* __restrict__ wo,
                       const float* __restrict__ w1, const float* __restrict__ w2)
{
    int i = blockIdx.x*256 + threadIdx.x;
    if (i < DIMM*DIMM) {
        int k = i >> 10, n = i & 1023;
        g_wqkv[(size_t)k*QKVS + n]        = rndf(wq[i]);
        g_wqkv[(size_t)k*QKVS + 1024 + n] = rndf(wk[i]);
        g_wqkv[(size_t)k*QKVS + 2048 + n] = rndf(wv[i]);
        g_wo[i] = rndf(wo[i]);
    }
    size_t stride = (size_t)gridDim.x*256;
    for (size_t j = i; j < (size_t)DIMM*FFD; j += stride) {
        g_w1[j] = rndf(w1[j]);
        g_w2[j] = rndf(w2[j]);
    }
}

// ---------------- modulation vectors: s = silu(temb) @ W + b ----------------
__global__ void k_mod(const float* __restrict__ temb,
                      const float* __restrict__ w1, const float* __restrict__ b1,
                      const float* __restrict__ w2, const float* __restrict__ b2)
{
    int j   = blockIdx.x * 256 + threadIdx.x;
    int b   = blockIdx.y;
    int set = blockIdx.z;
    const float* W  = set ? w2 : w1;
    const float* Bb = set ? b2 : b1;
    float* out      = set ? g_s2 : g_s1;
    __shared__ float st[TDIM];
    for (int i = threadIdx.x; i < TDIM; i += 256) {
        float x = temb[b*TDIM + i];
        st[i] = x / (1.f + __expf(-x));
    }
    __syncthreads();
    float acc = Bb[j];
    for (int k = 0; k < TDIM; k++)
        acc += st[k] * W[(size_t)k*6*DIMM + j];
    out[b*6*DIMM + j] = acc;
}

// ---------------- LayerNorm + adaLN modulation -> g_x (tf32-rounded, GEMM-only) ----------------
__global__ void k_ln_mod(const float* __restrict__ e_in, const float* __restrict__ h_in,
                         const float* __restrict__ c_in, int use_res, int use_s2,
                         const float* __restrict__ lnw, const float* __restrict__ lnb)
{
    int r = blockIdx.x, tid = threadIdx.x;
    int b, sh_c, sc_c;
    const float* src;
    if (r < RMAIN) {
        b = r / SEQ; int s = r - b*SEQ;
        if (use_res) src = g_res + (size_t)r*DIMM;
        else src = (s < TXT) ? e_in + ((size_t)b*TXT + s)*DIMM
                             : h_in + ((size_t)b*IMGL + (s - TXT))*DIMM;
        if (s < TXT) { sh_c = 3; sc_c = 4; } else { sh_c = 0; sc_c = 1; }
    } else {
        int qq = r - RMAIN; b = qq / NCPT;
        src = use_res ? g_res + (size_t)r*DIMM : c_in + (size_t)qq*DIMM;
        sh_c = 3; sc_c = 4;
    }
    __shared__ float xs[DIMM];
    __shared__ float red[32];
    float ls = 0.f, lq = 0.f;
    #pragma unroll
    for (int i = 0; i < 4; i++) {
        float x = src[tid + i*256];
        xs[tid + i*256] = x;
        ls += x; lq += x*x;
    }
    float ts = blockReduceSum(ls, red);
    float tq = blockReduceSum(lq, red);
    float mu   = ts * (1.f/DIMM);
    float var  = tq * (1.f/DIMM) - mu*mu;
    float rstd = rsqrtf(var + 1e-5f);
    const float* S  = (use_s2 ? g_s2 : g_s1) + b*6*DIMM;
    #pragma unroll
    for (int i = 0; i < 4; i++) {
        int j = tid + i*256;
        float y = (xs[j] - mu)*rstd*lnw[j] + lnb[j];
        y = y * (1.f + S[sc_c*DIMM + j]) + S[sh_c*DIMM + j];
        g_x[(size_t)r*DIMM + j] = rndf(y);
    }
}

// ---------------- TF32 GEMM: 128x128, cp.async 3-stage + ldmatrix, fused epilogues ----------------
// EPI: 0 plain, 1 resid1 (g_res = src + gate1*v). z-split via zA/zB/zC offsets.
#define ASTR 36
#define BSTRG 136
#define ABYTES (128*ASTR*4)
#define BBYTES (32*BSTRG*4)
#define STAGE_BYTES (ABYTES + BBYTES)
#define SMEM_GEMM (3*STAGE_BYTES)

__device__ __forceinline__ void cp16(unsigned sm, const float* gp, unsigned sz) {
    asm volatile("cp.async.ca.shared.global [%0], [%1], 16, %2;\n" :: "r"(sm), "l"(gp), "r"(sz));
}
__device__ __forceinline__ uint4 ldm4(unsigned addr) {
    uint4 r;
    asm volatile("ldmatrix.sync.aligned.m8n8.x4.shared.b16 {%0,%1,%2,%3}, [%4];\n"
        : "=r"(r.x), "=r"(r.y), "=r"(r.z), "=r"(r.w) : "r"(addr));
    return r;
}

template<int ACT, int ROUND, int EPI>
__global__ void __launch_bounds__(256, 2)
mma_gemm(const float* __restrict__ A, const float* __restrict__ B,
         const float* __restrict__ bias, float* __restrict__ C,
         int M, int N, int K, int lda, int ldb, int ldc,
         const float* __restrict__ ep_e, const float* __restrict__ ep_h,
         const float* __restrict__ ep_c,
         long zA, long zB, long zC)
{
    extern __shared__ __align__(16) char smem_raw[];
    unsigned smem_base = (unsigned)__cvta_generic_to_shared(smem_raw);

    int z = blockIdx.z;
    A += (long)z*zA; B += (long)z*zB; C += (long)z*zC;

    int m0 = blockIdx.y*128, n0 = blockIdx.x*128;
    int tid = threadIdx.x, lane = tid & 31, w = tid >> 5;
    int wm = w & 1, wn = w >> 1;
    int g = lane >> 2, c = lane & 3;

    int arow = tid >> 1;
    int acol = (tid & 1) * 16;
    int gmrow = m0 + arow;
    const float* agp = A + (long)(gmrow < M ? gmrow : 0)*lda + acol;
    unsigned apred = (gmrow < M) ? 16u : 0u;
    unsigned asm0 = smem_base + (unsigned)(arow*ASTR + acol)*4u;
    int bkr = tid >> 3;
    int bcol = (tid & 7) * 16;
    const float* bgp = B + (long)bkr*ldb + n0 + bcol;
    unsigned bsm0 = smem_base + (unsigned)ABYTES + (unsigned)(bkr*BSTRG + bcol)*4u;

    unsigned a_lane = (unsigned)(((((lane>>3)&1)*8 + (lane&7))*ASTR + (lane>>4)*4)*4);

    float acc[4][4][4];
    #pragma unroll
    for (int i = 0; i < 4; i++)
        #pragma unroll
        for (int j = 0; j < 4; j++)
            #pragma unroll
            for (int k = 0; k < 4; k++) acc[i][j][k] = 0.f;

    int ntile = K >> 5;

#define ISSUE(KT, BUF)                                                         \
    {                                                                          \
        unsigned so = (unsigned)(BUF)*STAGE_BYTES;                             \
        const float* ag = agp + (KT)*32;                                       \
        _Pragma("unroll")                                                      \
        for (int j = 0; j < 4; j++) cp16(asm0 + so + j*16, ag + j*4, apred);   \
        const float* bg = bgp + (long)(KT)*32*ldb;                             \
        _Pragma("unroll")                                                      \
        for (int j = 0; j < 4; j++) cp16(bsm0 + so + j*16, bg + j*4, 16u);     \
        asm volatile("cp.async.commit_group;\n");                              \
    }

    ISSUE(0, 0);
    ISSUE(1, 1);

    for (int kt = 0; kt < ntile; kt++) {
        int buf = kt % 3;
        asm volatile("cp.async.wait_group 1;\n" ::: "memory");
        __syncthreads();

        unsigned Abase = smem_base + (unsigned)buf*STAGE_BYTES + a_lane
                       + (unsigned)(wm*64*ASTR)*4u;
        const unsigned* Bp = (const unsigned*)(smem_raw + buf*STAGE_BYTES + ABYTES);

        #pragma unroll
        for (int ks = 0; ks < 4; ks++) {
            uint4 a[4];
            #pragma unroll
            for (int mt = 0; mt < 4; mt++)
                a[mt] = ldm4(Abase + (unsigned)((mt*16*ASTR + ks*8)*4));
            int kc = ks*8 + c;
            unsigned b[4][2];
            #pragma unroll
            for (int nt = 0; nt < 4; nt++) {
                int nb = wn*32 + nt*8 + g;
                b[nt][0] = Bp[kc*BSTRG + nb];
                b[nt][1] = Bp[(kc+4)*BSTRG + nb];
            }
            #pragma unroll
            for (int mt = 0; mt < 4; mt++)
                #pragma unroll
                for (int nt = 0; nt < 4; nt++) {
                    asm volatile(
                        "mma.sync.aligned.m16n8k8.row.col.f32.tf32.tf32.f32 "
                        "{%0,%1,%2,%3}, {%4,%5,%6,%7}, {%8,%9}, {%0,%1,%2,%3};\n"
                        : "+f"(acc[mt][nt][0]), "+f"(acc[mt][nt][1]),
                          "+f"(acc[mt][nt][2]), "+f"(acc[mt][nt][3])
                        : "r"(a[mt].x), "r"(a[mt].y), "r"(a[mt].z), "r"(a[mt].w),
                          "r"(b[nt][0]), "r"(b[nt][1]));
                }
        }
        if (kt + 2 < ntile) { ISSUE(kt + 2, (kt + 2) % 3); }
        else asm volatile("cp.async.commit_group;\n");
    }
#undef ISSUE

    // ---- epilogue ----
    #pragma unroll
    for (int mt = 0; mt < 4; mt++) {
        #pragma unroll
        for (int half = 0; half < 2; half++) {
            int rr = m0 + wm*64 + mt*16 + g + half*8;
            if (rr >= M) continue;
            const float* srcrow = nullptr;
            const float* grow   = nullptr;
            if (EPI == 1) {
                int b, gcol; long off;
                if (rr < RMAIN) {
                    b = rr / SEQ; int s = rr - b*SEQ;
                    if (s < TXT) { gcol = 5; off = ((long)b*TXT + s)*DIMM; srcrow = ep_e + off; }
                    else         { gcol = 2; off = ((long)b*IMGL + (s - TXT))*DIMM; srcrow = ep_h + off; }
                } else {
                    int qq = rr - RMAIN; b = qq / NCPT; gcol = 5;
                    srcrow = ep_c + (long)qq*DIMM;
                }
                grow = g_s1 + b*6*DIMM + gcol*DIMM;
            }
            #pragma unroll
            for (int nt = 0; nt < 4; nt++) {
                int c0 = n0 + wn*32 + nt*8 + 2*c;
                if (c0 >= N) continue;
                float v0 = acc[mt][nt][half*2 + 0];
                float v1 = acc[mt][nt][half*2 + 1];
                if (bias) { v0 += bias[c0]; v1 += bias[c0+1]; }
                if (ACT == 1) {
                    float u = v0;
                    v0 = 0.5f*u*(1.f + tanhf(0.79788456080286535588f*(u + 0.044715f*u*u*u)));
                    u = v1;
                    v1 = 0.5f*u*(1.f + tanhf(0.79788456080286535588f*(u + 0.044715f*u*u*u)));
                }
                if (ROUND) { v0 = rndf(v0); v1 = rndf(v1); }
                if (EPI == 0) {
                    *(float2*)&C[(long)rr*ldc + c0] = make_float2(v0, v1);
                } else {
                    float2 sv = *(const float2*)&srcrow[c0];
                    float2 gv = *(const float2*)&grow[c0];
                    *(float2*)&g_res[(size_t)rr*DIMM + c0] =
                        make_float2(sv.x + gv.x*v0, sv.y + gv.y*v1);
                }
            }
        }
    }
}

// ---------------- split-K FF2 reduce (4 partials) + resid2 -> final outputs ----------------
__global__ void k_ff2red(float* __restrict__ out, const float* __restrict__ bias)
{
    int r = blockIdx.x, t = threadIdx.x;
    float* dst; int b, gcol;
    if (r < RMAIN) {
        b = r / SEQ; int s = r - b*SEQ;
        if (s < TXT) { dst = out + OE + ((size_t)b*TXT + s)*DIMM; gcol = 5; }
        else         { dst = out + ((size_t)b*IMGL + (s - TXT))*DIMM; gcol = 2; }
    } else {
        int qq = r - RMAIN; b = qq / NCPT;
        dst = out + OC + (size_t)qq*DIMM; gcol = 5;
    }
    const float* g = g_s2 + b*6*DIMM + gcol*DIMM;
    #pragma unroll
    for (int i = 0; i < 4; i++) {
        int j = t + i*256;
        float v = (g_part[(size_t)r*DIMM + j]
                +  g_part[(size_t)(RTOT + r)*DIMM + j])
                + (g_part[(size_t)(2*RTOT + r)*DIMM + j]
                +  g_part[(size_t)(3*RTOT + r)*DIMM + j]) + bias[j];
        dst[j] = g_res[(size_t)r*DIMM + j] + g[j]*v;
    }
}

// ---------------- fused flash attention over g_qkv (stride 3072) ----------------
#define KSTR 68
#define VSTR 65
#define PSTR 68
#define FLASH_SMEM ((64*KSTR + 64*VSTR + 8*16*PSTR)*4)

__global__ void __launch_bounds__(256, 2)
k_flash(const float* __restrict__ qkv, float* __restrict__ og)
{
    extern __shared__ __align__(16) unsigned fsm[];
    unsigned* Ks = fsm;
    unsigned* Vs = Ks + 64*KSTR;
    unsigned* Ps = Vs + 64*VSTR;

    const float* qg = qkv;
    const float* kg = qkv + 1024;
    const float* vg = qkv + 2048;

    int b = blockIdx.y >> 4, h = blockIdx.y & 15;
    int tid = threadIdx.x, lane = tid & 31, w = tid >> 5;
    int g = lane >> 2, c = lane & 3;
    int r0 = blockIdx.x*128 + w*16 + g;
    int r1 = r0 + 8;
    bool v0 = r0 < SEQ, v1 = r1 < SEQ;

    unsigned qf[8][4];
    {
        const float* q0 = qg + (size_t)(b*SEQ + (v0 ? r0 : 0))*QKVS + h*HD;
        const float* q1 = qg + (size_t)(b*SEQ + (v1 ? r1 : 0))*QKVS + h*HD;
        #pragma unroll
        for (int ks = 0; ks < 8; ks++) {
            qf[ks][0] = v0 ? f2tf32(q0[ks*8 + c])     : 0u;
            qf[ks][1] = v1 ? f2tf32(q1[ks*8 + c])     : 0u;
            qf[ks][2] = v0 ? f2tf32(q0[ks*8 + c + 4]) : 0u;
            qf[ks][3] = v1 ? f2tf32(q1[ks*8 + c + 4]) : 0u;
        }
    }

    float mr0 = -1e30f, mr1 = -1e30f;
    float lr0 = 0.f, lr1 = 0.f;
    float O[8][4];
    #pragma unroll
    for (int i = 0; i < 8; i++)
        #pragma unroll
        for (int j = 0; j < 4; j++) O[i][j] = 0.f;

    int kk = tid & 63;
    int dg = (tid >> 6) * 16;
    unsigned* Pw = Ps + w*16*PSTR;

    const int NTILES = (SEQ + 63) / 64;
    for (int t = 0; t < NTILES; t++) {
        __syncthreads();
        {
            int j = t*64 + kk;
            bool jv = j < SEQ;
            const float* kp = kg + (size_t)(b*SEQ + (jv ? j : 0))*QKVS + h*HD + dg;
            const float* vp = vg + (size_t)(b*SEQ + (jv ? j : 0))*QKVS + h*HD + dg;
            #pragma unroll
            for (int i = 0; i < 4; i++) {
                float4 k4 = jv ? *(const float4*)(kp + i*4) : make_float4(0,0,0,0);
                float4 w4 = jv ? *(const float4*)(vp + i*4) : make_float4(0,0,0,0);
                int d = dg + i*4;
                Ks[(d+0)*KSTR + kk] = f2tf32(k4.x);
                Ks[(d+1)*KSTR + kk] = f2tf32(k4.y);
                Ks[(d+2)*KSTR + kk] = f2tf32(k4.z);
                Ks[(d+3)*KSTR + kk] = f2tf32(k4.w);
                Vs[kk*VSTR + d+0] = f2tf32(w4.x);
                Vs[kk*VSTR + d+1] = f2tf32(w4.y);
                Vs[kk*VSTR + d+2] = f2tf32(w4.z);
                Vs[kk*VSTR + d+3] = f2tf32(w4.w);
            }
        }
        __syncthreads();

        float s[8][4];
        #pragma unroll
        for (int i = 0; i < 8; i++)
            #pragma unroll
            for (int j = 0; j < 4; j++) s[i][j] = 0.f;
        #pragma unroll
        for (int ks = 0; ks < 8; ks++) {
            int kc = ks*8 + c;
            #pragma unroll
            for (int nt = 0; nt < 8; nt++) {
                unsigned b0 = Ks[kc*KSTR + nt*8 + g];
                unsigned b1 = Ks[(kc+4)*KSTR + nt*8 + g];
                asm volatile(
                    "mma.sync.aligned.m16n8k8.row.col.f32.tf32.tf32.f32 "
                    "{%0,%1,%2,%3}, {%4,%5,%6,%7}, {%8,%9}, {%0,%1,%2,%3};\n"
                    : "+f"(s[nt][0]), "+f"(s[nt][1]), "+f"(s[nt][2]), "+f"(s[nt][3])
                    : "r"(qf[ks][0]), "r"(qf[ks][1]), "r"(qf[ks][2]), "r"(qf[ks][3]),
                      "r"(b0), "r"(b1));
            }
        }

        int jb = t*64 + 2*c;
        #pragma unroll
        for (int nt = 0; nt < 8; nt++) {
            int j0 = jb + nt*8, j1 = j0 + 1;
            s[nt][0] = (j0 < SEQ) ? s[nt][0]*0.125f : -1e30f;
            s[nt][1] = (j1 < SEQ) ? s[nt][1]*0.125f : -1e30f;
            s[nt][2] = (j0 < SEQ) ? s[nt][2]*0.125f : -1e30f;
            s[nt][3] = (j1 < SEQ) ? s[nt][3]*0.125f : -1e30f;
        }
        float mx0 = -1e30f, mx1 = -1e30f;
        #pragma unroll
        for (int nt = 0; nt < 8; nt++) {
            mx0 = fmaxf(mx0, fmaxf(s[nt][0], s[nt][1]));
            mx1 = fmaxf(mx1, fmaxf(s[nt][2], s[nt][3]));
        }
        mx0 = fmaxf(mx0, __shfl_xor_sync(0xffffffffu, mx0, 1));
        mx0 = fmaxf(mx0, __shfl_xor_sync(0xffffffffu, mx0, 2));
        mx1 = fmaxf(mx1, __shfl_xor_sync(0xffffffffu, mx1, 1));
        mx1 = fmaxf(mx1, __shfl_xor_sync(0xffffffffu, mx1, 2));
        float nm0 = fmaxf(mr0, mx0), nm1 = fmaxf(mr1, mx1);
        float sc0 = __expf(mr0 - nm0), sc1 = __expf(mr1 - nm1);
        float rs0 = 0.f, rs1 = 0.f;
        #pragma unroll
        for (int nt = 0; nt < 8; nt++) {
            float p0 = __expf(s[nt][0] - nm0);
            float p1 = __expf(s[nt][1] - nm0);
            float p2 = __expf(s[nt][2] - nm1);
            float p3 = __expf(s[nt][3] - nm1);
            rs0 += p0 + p1; rs1 += p2 + p3;
            int col = nt*8 + 2*c;
            *(uint2*)&Pw[g*PSTR + col]     = make_uint2(f2tf32(p0), f2tf32(p1));
            *(uint2*)&Pw[(g+8)*PSTR + col] = make_uint2(f2tf32(p2), f2tf32(p3));
        }
        rs0 += __shfl_xor_sync(0xffffffffu, rs0, 1);
        rs0 += __shfl_xor_sync(0xffffffffu, rs0, 2);
        rs1 += __shfl_xor_sync(0xffffffffu, rs1, 1);
        rs1 += __shfl_xor_sync(0xffffffffu, rs1, 2);
        lr0 = lr0*sc0 + rs0;
        lr1 = lr1*sc1 + rs1;
        mr0 = nm0; mr1 = nm1;
        #pragma unroll
        for (int nt = 0; nt < 8; nt++) {
            O[nt][0] *= sc0; O[nt][1] *= sc0;
            O[nt][2] *= sc1; O[nt][3] *= sc1;
        }
        __syncwarp();

        #pragma unroll
        for (int ks = 0; ks < 8; ks++) {
            int kc = ks*8 + c;
            unsigned a0 = Pw[g*PSTR + kc];
            unsigned a1 = Pw[(g+8)*PSTR + kc];
            unsigned a2 = Pw[g*PSTR + kc + 4];
            unsigned a3 = Pw[(g+8)*PSTR + kc + 4];
            #pragma unroll
            for (int nt = 0; nt < 8; nt++) {
                unsigned b0 = Vs[kc*VSTR + nt*8 + g];
                unsigned b1 = Vs[(kc+4)*VSTR + nt*8 + g];
                asm volatile(
                    "mma.sync.aligned.m16n8k8.row.col.f32.tf32.tf32.f32 "
                    "{%0,%1,%2,%3}, {%4,%5,%6,%7}, {%8,%9}, {%0,%1,%2,%3};\n"
                    : "+f"(O[nt][0]), "+f"(O[nt][1]), "+f"(O[nt][2]), "+f"(O[nt][3])
                    : "r"(a0), "r"(a1), "r"(a2), "r"(a3),
                      "r"(b0), "r"(b1));
            }
        }
        __syncwarp();
    }

    float i0 = 1.f/lr0, i1 = 1.f/lr1;
    if (v0) {
        float* op = og + (size_t)(b*SEQ + r0)*DIMM + h*HD;
        #pragma unroll
        for (int nt = 0; nt < 8; nt++)
            *(float2*)&op[nt*8 + 2*c] = make_float2(O[nt][0]*i0, O[nt][1]*i0);
    }
    if (v1) {
        float* op = og + (size_t)(b*SEQ + r1)*DIMM + h*HD;
        #pragma unroll
        for (int nt = 0; nt < 8; nt++)
            *(float2*)&op[nt*8 + 2*c] = make_float2(O[nt][2]*i1, O[nt][3]*i1);
    }
}

// ---------------- per-head LN (+RoPE) on q/k within g_qkv (full fp32 out) ----------------
__global__ void k_headln(float* __restrict__ x, const float* __restrict__ nw,
                         const float* __restrict__ nb,
                         const float* __restrict__ rc, const float* __restrict__ rs)
{
    int w = blockIdx.x * 8 + (threadIdx.x >> 5);
    if (w >= RTOT*HEADS) return;
    int lane = threadIdx.x & 31;
    int r = w >> 4, h = w & 15;
    float* p = x + (size_t)r*QKVS + h*HD;
    float v0 = p[lane], v1 = p[lane + 32];
    float s = v0 + v1;
    #pragma unroll
    for (int o = 16; o; o >>= 1) s += __shfl_xor_sync(0xffffffffu, s, o);
    float mu = s * (1.f/64.f);
    float d0 = v0 - mu, d1 = v1 - mu;
    float qv = d0*d0 + d1*d1;
    #pragma unroll
    for (int o = 16; o; o >>= 1) qv += __shfl_xor_sync(0xffffffffu, qv, o);
    float rstd = rsqrtf(qv*(1.f/64.f) + 1e-6f);
    float y0 = d0*rstd*nw[lane]    + nb[lane];
    float y1 = d1*rstd*nw[lane+32] + nb[lane+32];
    if (r < RMAIN) {
        int sidx = r % SEQ;
        if (sidx >= TXT) {
            int pos = sidx - TXT;
            const float* c  = rc + (size_t)pos*HD;
            const float* sn = rs + (size_t)pos*HD;
            float p0 = __shfl_xor_sync(0xffffffffu, y0, 1);
            float p1 = __shfl_xor_sync(0xffffffffu, y1, 1);
            float r0 = (lane & 1) ? p0 : -p0;
            float r1 = (lane & 1) ? p1 : -p1;
            y0 = y0*c[lane]    + r0*sn[lane];
            y1 = y1*c[lane+32] + r1*sn[lane+32];
        }
    }
    p[lane] = y0; p[lane+32] = y1;
}

// ---------------- concept attention: scores+softmax per (b,h,c) ----------------
__global__ void k_cscore(const float* __restrict__ qkv)
{
    int bid = blockIdx.x;
    int b = bid >> 7, h = (bid >> 3) & 15, c = bid & 7;
    int t = threadIdx.x;
    __shared__ float qs[HD];
    __shared__ float red[32];
    const float* qrow = qkv + (size_t)(RMAIN + b*NCPT + c)*QKVS + h*HD;
    if (t < HD) qs[t] = qrow[t];
    __syncthreads();
    float v[7];
    float m = -1e30f;
    #pragma unroll
    for (int i = 0; i < 7; i++) {
        int j = t + i*256;
        if (j < CKEYS) {
            const float* krow = (j < NCPT)
                ? qkv + (size_t)(RMAIN + b*NCPT + j)*QKVS + 1024 + h*HD
                : qkv + (size_t)(b*SEQ + TXT + (j - NCPT))*QKVS + 1024 + h*HD;
            float a = 0.f;
            for (int d = 0; d < HD; d++) a += qs[d]*krow[d];
            v[i] = a*0.125f;
        } else v[i] = -1e30f;
        m = fmaxf(m, v[i]);
    }
    m = blockReduceMax(m, red);
    float s = 0.f;
    #pragma unroll
    for (int i = 0; i < 7; i++) {
        int j = t + i*256;
        v[i] = (j < CKEYS) ? __expf(v[i]-m) : 0.f;
        s += v[i];
    }
    s = blockReduceSum(s, red);
    float inv = 1.f/s;
    float* out = g_cs + ((size_t)(b*HEADS + h)*NCPT + c)*CKEYS;
    #pragma unroll
    for (int i = 0; i < 7; i++) {
        int j = t + i*256;
        if (j < CKEYS) out[j] = v[i]*inv;
    }
}

__global__ void k_cpv(const float* __restrict__ qkv)
{
    int bid = blockIdx.x; int b = bid >> 7, h = (bid >> 3) & 15, c = bid & 7;
    int t = threadIdx.x;
    int d  = t & 63;
    int jg = t >> 6;
    const float* p = g_cs + ((size_t)(b*HEADS + h)*NCPT + c)*CKEYS;
    float acc = 0.f;
    for (int j = jg; j < CKEYS; j += 4) {
        const float* vrow = (j < NCPT)
            ? qkv + (size_t)(RMAIN + b*NCPT + j)*QKVS + 2048 + h*HD
            : qkv + (size_t)(b*SEQ + TXT + (j - NCPT))*QKVS + 2048 + h*HD;
        acc += p[j]*vrow[d];
    }
    __shared__ float part[4][64];
    part[jg][d] = acc;
    __syncthreads();
    if (t < 64)
        g_attn[(size_t)(RMAIN + b*NCPT + c)*DIMM + h*HD + t] =
            part[0][t] + part[1][t] + part[2][t] + part[3][t];
}

// ---------------- head score (batch 1), top-k ----------------
__global__ void k_headscore()
{
    int h = blockIdx.x, t = threadIdx.x;
    float s1 = 0.f, s2 = 0.f;
    for (int p = t; p < IMGL; p += 256) {
        const float* row = g_attn + (size_t)(SEQ + TXT + p)*DIMM + h*HD;
        float m = 0.f;
        for (int d = 0; d < HD; d++) m += row[d];
        m *= (1.f/64.f);
        s1 += m; s2 += m*m;
    }
    __shared__ float red[32];
    s1 = blockReduceSum(s1, red);
    s2 = blockReduceSum(s2, red);
    if (t == 0) {
        float mu = s1/IMGL;
        g_hscore[h] = sqrtf(fmaxf(s2/IMGL - mu*mu, 0.f));
    }
}

__global__ void k_topk()
{
    if (threadIdx.x) return;
    bool used[HEADS] = {};
    for (int i = 0; i < 4; i++) {
        int bi = -1; float bv = -1e30f;
        for (int hh = 0; hh < HEADS; hh++)
            if (!used[hh] && g_hscore[hh] > bv) { bv = g_hscore[hh]; bi = hh; }
        used[bi] = true; g_selhead[i] = bi;
    }
}

// ---------------- sim argmax over patches per (h, concept, frame) ----------------
__global__ void k_simargmax(const float* __restrict__ qkv)
{
    int h = blockIdx.x, tc = blockIdx.y, f = blockIdx.z;
    int t = threadIdx.x;
    __shared__ float ks[HD];
    if (t < HD) ks[t] = qkv[(size_t)(RMAIN + NCPT + tc)*QKVS + 1024 + h*HD + t];
    __syncthreads();
    float bv = -1e30f; int bi = 0;
    #pragma unroll
    for (int i = 0; i < 3; i++) {
        int p = t + i*128;
        const float* qrow = qkv + (size_t)(SEQ + TXT + f*PATCHES + p)*QKVS + h*HD;
        float a = 0.f;
        for (int d = 0; d < HD; d++) a += qrow[d]*ks[d];
        if (a > bv) { bv = a; bi = p; }
    }
    __shared__ float sv[128]; __shared__ int si[128];
    sv[t] = bv; si[t] = bi;
    __syncthreads();
    for (int o = 64; o; o >>= 1) {
        if (t < o) {
            if (sv[t+o] > sv[t] || (sv[t+o] == sv[t] && si[t+o] < si[t])) {
                sv[t] = sv[t+o]; si[t] = si[t+o];
            }
        }
        __syncthreads();
    }
    if (t == 0) g_selvis[(h*NCPT + tc)*FRAMES + f] = si[0];
}

// ---------------- imap per (h, f) ----------------
__global__ void k_imap()
{
    int h = blockIdx.x, f = blockIdx.y;
    int t = threadIdx.x;
    __shared__ float sel[NCPT][HD];
    for (int idx = t; idx < NCPT*HD; idx += 384) {
        int tc = idx >> 6, d = idx & 63;
        int sp = g_selvis[(h*NCPT + tc)*FRAMES + f];
        sel[tc][d] = g_attn[(size_t)(SEQ + TXT + f*PATCHES + sp)*DIMM + h*HD + d];
    }
    __syncthreads();
    const float* row = g_attn + (size_t)(SEQ + TXT + f*PATCHES + t)*DIMM + h*HD;
    float a[NCPT] = {};
    for (int d = 0; d < HD; d++) {
        float x = row[d];
        #pragma unroll
        for (int tc = 0; tc < NCPT; tc++) a[tc] += sel[tc][d]*x;
    }
    float mu = 0.f;
    #pragma unroll
    for (int tc = 0; tc < NCPT; tc++) mu += a[tc];
    mu *= (1.f/8.f);
    float var = 0.f;
    #pragma unroll
    for (int tc = 0; tc < NCPT; tc++) { float d_ = a[tc]-mu; var += d_*d_; }
    float sd = sqrtf(var*(1.f/7.f)) + 1e-6f;
    #pragma unroll
    for (int tc = 0; tc < NCPT; tc++)
        g_imap[((size_t)(h*NCPT + tc))*IMGL + f*PATCHES + t] = (a[tc]-mu)/sd;
}

__global__ void k_selfinal(float* __restrict__ out)
{
    int idx = blockIdx.x*256 + threadIdx.x;
    if (idx >= NCPT*IMGL) return;
    int tc = idx / IMGL, p = idx % IMGL;
    float ssum = 0.f;
    for (int i = 0; i < 4; i++)
        ssum += g_imap[((size_t)(g_selhead[i]*NCPT + tc))*IMGL + p];
    out[OSEL + idx] = ssum*0.25f;
    float tot = 0.f;
    for (int h = 0; h < HEADS; h++)
        tot += g_imap[((size_t)(h*NCPT + tc))*IMGL + p];
    out[OIMAP + idx] = tot;
}

// ---------------- cross/concept maps ----------------
__global__ void k_dotmaps(const float* __restrict__ A, const float* __restrict__ Brows,
                          int lda, int ldb, float* __restrict__ out, float scale)
{
    int w = blockIdx.x*8 + (threadIdx.x >> 5);
    if (w >= NCPT*IMGL) return;
    int lane = threadIdx.x & 31;
    int c = w / IMGL, p = w % IMGL;
    const float* a = A     + (size_t)(SEQ + TXT + p)*lda;
    const float* b = Brows + (size_t)(RMAIN + NCPT + c)*ldb;
    float s = 0.f;
    for (int i = lane; i < DIMM; i += 32) s += a[i]*b[i];
    #pragma unroll
    for (int o = 16; o; o >>= 1) s += __shfl_xor_sync(0xffffffffu, s, o);
    if (lane == 0) out[c*IMGL + p] = s*scale;
}

// ---------------- host launcher ----------------
static float* symf(const void* symbol) {
    void* p = nullptr;
    cudaGetSymbolAddress(&p, symbol);
    return (float*)p;
}

extern "C" void kernel_launch(void* const* d_in, const int* in_sizes, int n_in,
                              void* d_out, int out_size)
{
    const float* h_in  = (const float*)d_in[0];
    const float* e_in  = (const float*)d_in[1];
    const float* c_in  = (const float*)d_in[2];
    const float* temb  = (const float*)d_in[3];
    const float* ropec = (const float*)d_in[4];
    const float* ropes = (const float*)d_in[5];
    const float* n1w   = (const float*)d_in[6];
    const float* n1b   = (const float*)d_in[7];
    const float* ln1w  = (const float*)d_in[8];
    const float* ln1b  = (const float*)d_in[9];
    const float* n2w   = (const float*)d_in[10];
    const float* n2b   = (const float*)d_in[11];
    const float* ln2w  = (const float*)d_in[12];
    const float* ln2b  = (const float*)d_in[13];
    const float* wq    = (const float*)d_in[14];
    const float* wk    = (const float*)d_in[15];
    const float* wv    = (const float*)d_in[16];
    const float* nqw   = (const float*)d_in[17];
    const float* nqb   = (const float*)d_in[18];
    const float* nkw   = (const float*)d_in[19];
    const float* nkb   = (const float*)d_in[20];
    const float* wo    = (const float*)d_in[21];
    const float* bo    = (const float*)d_in[22];
    const float* ffw1  = (const float*)d_in[23];
    const float* ffb1  = (const float*)d_in[24];
    const float* ffw2  = (const float*)d_in[25];
    const float* ffb2  = (const float*)d_in[26];
    float* out = (float*)d_out;

    float* px    = symf(g_x);
    float* pqkv  = symf(g_qkv);
    float* pattn = symf(g_attn);
    float* pffh  = symf(g_ffh);
    float* ppart = symf(g_part);
    float* pwqkv = symf(g_wqkv);
    float* pwo   = symf(g_wo);
    float* pw1   = symf(g_w1);
    float* pw2   = symf(g_w2);

    cudaFuncSetAttribute(mma_gemm<0,0,0>, cudaFuncAttributeMaxDynamicSharedMemorySize, SMEM_GEMM);
    cudaFuncSetAttribute(mma_gemm<0,0,1>, cudaFuncAttributeMaxDynamicSharedMemorySize, SMEM_GEMM);
    cudaFuncSetAttribute(mma_gemm<1,1,0>, cudaFuncAttributeMaxDynamicSharedMemorySize, SMEM_GEMM);
    cudaFuncSetAttribute(k_flash, cudaFuncAttributeMaxDynamicSharedMemorySize, FLASH_SMEM);

    static cudaStream_t s1 = nullptr, s2 = nullptr;
    static cudaEvent_t e_prep, e_qkv, e_hq, e_hk, e_flash, e_cpv, e_sim, e_end1, e_end2;
    if (!s1) {
        cudaStreamCreateWithFlags(&s1, cudaStreamNonBlocking);
        cudaStreamCreateWithFlags(&s2, cudaStreamNonBlocking);
        cudaEventCreateWithFlags(&e_prep,  cudaEventDisableTiming);
        cudaEventCreateWithFlags(&e_qkv,   cudaEventDisableTiming);
        cudaEventCreateWithFlags(&e_hq,    cudaEventDisableTiming);
        cudaEventCreateWithFlags(&e_hk,    cudaEventDisableTiming);
        cudaEventCreateWithFlags(&e_flash, cudaEventDisableTiming);
        cudaEventCreateWithFlags(&e_cpv,   cudaEventDisableTiming);
        cudaEventCreateWithFlags(&e_sim,   cudaEventDisableTiming);
        cudaEventCreateWithFlags(&e_end1,  cudaEventDisableTiming);
        cudaEventCreateWithFlags(&e_end2,  cudaEventDisableTiming);
    }
    cudaStream_t s0 = 0;

    // fork side streams from s0
    cudaEventRecord(e_qkv, s0);
    cudaStreamWaitEvent(s1, e_qkv, 0);
    cudaStreamWaitEvent(s2, e_qkv, 0);
    k_prep<<<4096, 256, 0, s1>>>(wq, wk, wv, wo, ffw1, ffw2);
    cudaEventRecord(e_prep, s1);

    k_mod<<<dim3(24,2,2), 256, 0, s0>>>(temb, n1w, n1b, n2w, n2b);
    k_ln_mod<<<RTOT, 256, 0, s0>>>(e_in, h_in, c_in, 0, 0, ln1w, ln1b);

    cudaStreamWaitEvent(s0, e_prep, 0);
    mma_gemm<0,0,0><<<dim3(24,28),256,SMEM_GEMM,s0>>>(px, pwqkv, nullptr, pqkv,
                                                      RTOT, QKVS, DIMM, DIMM, QKVS, QKVS,
                                                      nullptr, nullptr, nullptr, 0, 0, 0);
    cudaEventRecord(e_qkv, s0);

    cudaStreamWaitEvent(s1, e_qkv, 0);
    k_headln<<<7080, 256, 0, s0>>>(pqkv,        nqw, nqb, ropec, ropes);
    cudaEventRecord(e_hq, s0);
    k_headln<<<7080, 256, 0, s1>>>(pqkv + 1024, nkw, nkb, ropec, ropes);
    cudaEventRecord(e_hk, s1);

    cudaStreamWaitEvent(s0, e_hk, 0);
    k_flash<<<dim3(14, 32), 256, FLASH_SMEM, s0>>>(pqkv, pattn);
    cudaEventRecord(e_flash, s0);

    cudaStreamWaitEvent(s1, e_hq, 0);
    k_cscore<<<256, 256, 0, s1>>>(pqkv);
    k_cpv<<<256, 256, 0, s1>>>(pqkv);
    cudaEventRecord(e_cpv, s1);

    cudaStreamWaitEvent(s2, e_hq, 0);
    cudaStreamWaitEvent(s2, e_hk, 0);
    k_simargmax<<<dim3(HEADS, NCPT, FRAMES), 128, 0, s2>>>(pqkv);
    cudaEventRecord(e_sim, s2);
    k_dotmaps<<<1536, 256, 0, s2>>>(pqkv, pqkv + 1024, QKVS, QKVS, out + OXMAP, 1.f/16.f);
    cudaStreamWaitEvent(s2, e_flash, 0);
    cudaStreamWaitEvent(s2, e_cpv, 0);
    k_dotmaps<<<1536, 256, 0, s2>>>(pattn, pattn, DIMM, DIMM, out + OCMAP, 1.f);
    cudaEventRecord(e_end2, s2);

    cudaStreamWaitEvent(s1, e_flash, 0);
    k_headscore<<<HEADS, 256, 0, s1>>>();
    k_topk<<<1, 32, 0, s1>>>();
    cudaStreamWaitEvent(s1, e_sim, 0);
    k_imap<<<dim3(HEADS, FRAMES), PATCHES, 0, s1>>>();
    k_selfinal<<<48, 256, 0, s1>>>(out);
    cudaEventRecord(e_end1, s1);

    // Wo projection: unsplit, fused resid1 epilogue -> writes g_res directly
    cudaStreamWaitEvent(s0, e_cpv, 0);
    mma_gemm<0,0,1><<<dim3(8,28),256,SMEM_GEMM,s0>>>(pattn, pwo, bo, out,
                                                     RTOT, DIMM, DIMM, DIMM, DIMM, DIMM,
                                                     e_in, h_in, c_in, 0, 0, 0);

    // LN phase 2, FF1, split-K=4 FF2 partials, reduce + resid2
    k_ln_mod<<<RTOT, 256, 0, s0>>>(e_in, h_in, c_in, 1, 1, ln2w, ln2b);
    mma_gemm<1,1,0><<<dim3(32,28),256,SMEM_GEMM,s0>>>(px, pw1, ffb1, pffh,
                                                      RTOT, FFD, DIMM, DIMM, FFD, FFD,
                                                      nullptr, nullptr, nullptr, 0, 0, 0);
    mma_gemm<0,0,0><<<dim3(8,28,4),256,SMEM_GEMM,s0>>>(pffh, pw2, nullptr, ppart,
                                                       RTOT, DIMM, 1024, FFD, DIMM, DIMM,
                                                       nullptr, nullptr, nullptr,
                                                       1024L, 1024L*DIMM, (long)RTOT*DIMM);
    k_ff2red<<<RTOT, 256, 0, s0>>>(out, ffb2);

    cudaStreamWaitEvent(s0, e_end1, 0);
    cudaStreamWaitEvent(s0, e_end2, 0);
}

// round 17
// speedup vs baseline: 1.0145x; 1.0076x over previous
#include <cuda_runtime.h>
#include <math.h>

#define HEADS   16
#define HD      64
#define DIMM    1024
#define QKVS    3072
#define TXT     226
#define IMGL    1536
#define SEQ     1762
#define NCPT    8
#define FRAMES  4
#define PATCHES 384
#define FFD     4096
#define TDIM    512
#define RMAIN   3524
#define RTOT    3540
#define CKEYS   1544

#define OE     3145728
#define OC     3608576
#define OSEL   3624960
#define OIMAP  3637248
#define OCMAP  3649536
#define OXMAP  3661824

// ---------------- device scratch ----------------
__device__ float g_s1[2*6*DIMM];
__device__ float g_s2[2*6*DIMM];
__device__ float g_x   [RTOT*DIMM];
__device__ float g_qkv [(size_t)RTOT*QKVS];
__device__ float g_attn[RTOT*DIMM];
__device__ float g_res [RTOT*DIMM];
__device__ float g_ffh [(size_t)RTOT*FFD];
__device__ float g_part[(size_t)4*RTOT*DIMM];
__device__ float g_wqkv[(size_t)DIMM*QKVS];
__device__ float g_wo  [(size_t)DIMM*DIMM];
__device__ float g_w1  [(size_t)DIMM*FFD];
__device__ float g_w2  [(size_t)FFD*DIMM];
__device__ float g_cs[(size_t)2*HEADS*NCPT*CKEYS];
__device__ float g_hscore[HEADS];
__device__ int   g_selhead[4];
__device__ int   g_selvis[HEADS*NCPT*FRAMES];
__device__ float g_imap[HEADS*NCPT*IMGL];

__device__ __forceinline__ unsigned f2tf32(float x) {
    unsigned u;
    asm("cvt.rna.tf32.f32 %0, %1;" : "=r"(u) : "f"(x));
    return u;
}
__device__ __forceinline__ float rndf(float x) { return __uint_as_float(f2tf32(x)); }

// ---------------- reductions ----------------
__device__ __forceinline__ float blockReduceSum(float v, float* red) {
    int lane = threadIdx.x & 31, w = threadIdx.x >> 5;
    #pragma unroll
    for (int o = 16; o; o >>= 1) v += __shfl_xor_sync(0xffffffffu, v, o);
    if (lane == 0) red[w] = v;
    __syncthreads();
    int nw = (blockDim.x + 31) >> 5;
    float r = (threadIdx.x < nw) ? red[threadIdx.x] : 0.f;
    if (w == 0) {
        #pragma unroll
        for (int o = 16; o; o >>= 1) r += __shfl_xor_sync(0xffffffffu, r, o);
        if (lane == 0) red[0] = r;
    }
    __syncthreads();
    r = red[0];
    __syncthreads();
    return r;
}

__device__ __forceinline__ float blockReduceMax(float v, float* red) {
    int lane = threadIdx.x & 31, w = threadIdx.x >> 5;
    #pragma unroll
    for (int o = 16; o; o >>= 1) v = fmaxf(v, __shfl_xor_sync(0xffffffffu, v, o));
    if (lane == 0) red[w] = v;
    __syncthreads();
    int nw = (blockDim.x + 31) >> 5;
    float r = (threadIdx.x < nw) ? red[threadIdx.x] : -1e30f;
    if (w == 0) {
        #pragma unroll
        for (int o = 16; o; o >>= 1) r = fmaxf(r, __shfl_xor_sync(0xffffffffu, r, o));
        if (lane == 0) red[0] = r;
    }
    __syncthreads();
    r = red[0];
    __syncthreads();
    return r;
}

// ---------------- weight prep: round to tf32 once ----------------
__global__ void k_prep(const float* __restrict__ wq, const float* __restrict__ wk,
                       const float* __restrict__ wv, const float* __restrict__ wo,
                       const float* __restrict__ w1, const float* __restrict__ w2)
{
    int i = blockIdx.x*256 + threadIdx.x;
    if (i < DIMM*DIMM) {
        int k = i >> 10, n = i & 1023;
        g_wqkv[(size_t)k*QKVS + n]        = rndf(wq[i]);
        g_wqkv[(size_t)k*QKVS + 1024 + n] = rndf(wk[i]);
        g_wqkv[(size_t)k*QKVS + 2048 + n] = rndf(wv[i]);
        g_wo[i] = rndf(wo[i]);
    }
    size_t stride = (size_t)gridDim.x*256;
    for (size_t j = i; j < (size_t)DIMM*FFD; j += stride) {
        g_w1[j] = rndf(w1[j]);
        g_w2[j] = rndf(w2[j]);
    }
}

// ---------------- modulation vectors: s = silu(temb) @ W + b ----------------
__global__ void k_mod(const float* __restrict__ temb,
                      const float* __restrict__ w1, const float* __restrict__ b1,
                      const float* __restrict__ w2, const float* __restrict__ b2)
{
    int j   = blockIdx.x * 256 + threadIdx.x;
    int b   = blockIdx.y;
    int set = blockIdx.z;
    const float* W  = set ? w2 : w1;
    const float* Bb = set ? b2 : b1;
    float* out      = set ? g_s2 : g_s1;
    __shared__ float st[TDIM];
    for (int i = threadIdx.x; i < TDIM; i += 256) {
        float x = temb[b*TDIM + i];
        st[i] = x / (1.f + __expf(-x));
    }
    __syncthreads();
    float acc = Bb[j];
    for (int k = 0; k < TDIM; k++)
        acc += st[k] * W[(size_t)k*6*DIMM + j];
    out[b*6*DIMM + j] = acc;
}

// ---------------- LayerNorm + adaLN modulation -> g_x (tf32-rounded, GEMM-only) ----------------
__global__ void k_ln_mod(const float* __restrict__ e_in, const float* __restrict__ h_in,
                         const float* __restrict__ c_in, int use_res, int use_s2,
                         const float* __restrict__ lnw, const float* __restrict__ lnb)
{
    int r = blockIdx.x, tid = threadIdx.x;
    int b, sh_c, sc_c;
    const float* src;
    if (r < RMAIN) {
        b = r / SEQ; int s = r - b*SEQ;
        if (use_res) src = g_res + (size_t)r*DIMM;
        else src = (s < TXT) ? e_in + ((size_t)b*TXT + s)*DIMM
                             : h_in + ((size_t)b*IMGL + (s - TXT))*DIMM;
        if (s < TXT) { sh_c = 3; sc_c = 4; } else { sh_c = 0; sc_c = 1; }
    } else {
        int qq = r - RMAIN; b = qq / NCPT;
        src = use_res ? g_res + (size_t)r*DIMM : c_in + (size_t)qq*DIMM;
        sh_c = 3; sc_c = 4;
    }
    __shared__ float xs[DIMM];
    __shared__ float red[32];
    float ls = 0.f, lq = 0.f;
    #pragma unroll
    for (int i = 0; i < 4; i++) {
        float x = src[tid + i*256];
        xs[tid + i*256] = x;
        ls += x; lq += x*x;
    }
    float ts = blockReduceSum(ls, red);
    float tq = blockReduceSum(lq, red);
    float mu   = ts * (1.f/DIMM);
    float var  = tq * (1.f/DIMM) - mu*mu;
    float rstd = rsqrtf(var + 1e-5f);
    const float* S  = (use_s2 ? g_s2 : g_s1) + b*6*DIMM;
    #pragma unroll
    for (int i = 0; i < 4; i++) {
        int j = tid + i*256;
        float y = (xs[j] - mu)*rstd*lnw[j] + lnb[j];
        y = y * (1.f + S[sc_c*DIMM + j]) + S[sh_c*DIMM + j];
        g_x[(size_t)r*DIMM + j] = rndf(y);
    }
}

// ---------------- TF32 GEMM: 128x128, cp.async 3-stage + ldmatrix, fused epilogues ----------------
// EPI: 0 plain, 1 resid1 (g_res = src + gate1*v). z-split via zA/zB/zC offsets.
#define ASTR 36
#define BSTRG 136
#define ABYTES (128*ASTR*4)
#define BBYTES (32*BSTRG*4)
#define STAGE_BYTES (ABYTES + BBYTES)
#define SMEM_GEMM (3*STAGE_BYTES)

__device__ __forceinline__ void cp16(unsigned sm, const float* gp, unsigned sz) {
    asm volatile("cp.async.ca.shared.global [%0], [%1], 16, %2;\n" :: "r"(sm), "l"(gp), "r"(sz));
}
__device__ __forceinline__ uint4 ldm4(unsigned addr) {
    uint4 r;
    asm volatile("ldmatrix.sync.aligned.m8n8.x4.shared.b16 {%0,%1,%2,%3}, [%4];\n"
        : "=r"(r.x), "=r"(r.y), "=r"(r.z), "=r"(r.w) : "r"(addr));
    return r;
}

template<int ACT, int ROUND, int EPI>
__global__ void __launch_bounds__(256, 2)
mma_gemm(const float* __restrict__ A, const float* __restrict__ B,
         const float* __restrict__ bias, float* __restrict__ C,
         int M, int N, int K, int lda, int ldb, int ldc,
         const float* __restrict__ ep_e, const float* __restrict__ ep_h,
         const float* __restrict__ ep_c,
         long zA, long zB, long zC)
{
    extern __shared__ __align__(16) char smem_raw[];
    unsigned smem_base = (unsigned)__cvta_generic_to_shared(smem_raw);

    int z = blockIdx.z;
    A += (long)z*zA; B += (long)z*zB; C += (long)z*zC;

    int m0 = blockIdx.y*128, n0 = blockIdx.x*128;
    int tid = threadIdx.x, lane = tid & 31, w = tid >> 5;
    int wm = w & 1, wn = w >> 1;
    int g = lane >> 2, c = lane & 3;

    int arow = tid >> 1;
    int acol = (tid & 1) * 16;
    int gmrow = m0 + arow;
    const float* agp = A + (long)(gmrow < M ? gmrow : 0)*lda + acol;
    unsigned apred = (gmrow < M) ? 16u : 0u;
    unsigned asm0 = smem_base + (unsigned)(arow*ASTR + acol)*4u;
    int bkr = tid >> 3;
    int bcol = (tid & 7) * 16;
    const float* bgp = B + (long)bkr*ldb + n0 + bcol;
    unsigned bsm0 = smem_base + (unsigned)ABYTES + (unsigned)(bkr*BSTRG + bcol)*4u;

    unsigned a_lane = (unsigned)(((((lane>>3)&1)*8 + (lane&7))*ASTR + (lane>>4)*4)*4);

    float acc[4][4][4];
    #pragma unroll
    for (int i = 0; i < 4; i++)
        #pragma unroll
        for (int j = 0; j < 4; j++)
            #pragma unroll
            for (int k = 0; k < 4; k++) acc[i][j][k] = 0.f;

    int ntile = K >> 5;

#define ISSUE(KT, BUF)                                                         \
    {                                                                          \
        unsigned so = (unsigned)(BUF)*STAGE_BYTES;                             \
        const float* ag = agp + (KT)*32;                                       \
        _Pragma("unroll")                                                      \
        for (int j = 0; j < 4; j++) cp16(asm0 + so + j*16, ag + j*4, apred);   \
        const float* bg = bgp + (long)(KT)*32*ldb;                             \
        _Pragma("unroll")                                                      \
        for (int j = 0; j < 4; j++) cp16(bsm0 + so + j*16, bg + j*4, 16u);     \
        asm volatile("cp.async.commit_group;\n");                              \
    }

    ISSUE(0, 0);
    ISSUE(1, 1);

    for (int kt = 0; kt < ntile; kt++) {
        int buf = kt % 3;
        asm volatile("cp.async.wait_group 1;\n" ::: "memory");
        __syncthreads();

        unsigned Abase = smem_base + (unsigned)buf*STAGE_BYTES + a_lane
                       + (unsigned)(wm*64*ASTR)*4u;
        const unsigned* Bp = (const unsigned*)(smem_raw + buf*STAGE_BYTES + ABYTES);

        #pragma unroll
        for (int ks = 0; ks < 4; ks++) {
            uint4 a[4];
            #pragma unroll
            for (int mt = 0; mt < 4; mt++)
                a[mt] = ldm4(Abase + (unsigned)((mt*16*ASTR + ks*8)*4));
            int kc = ks*8 + c;
            unsigned b[4][2];
            #pragma unroll
            for (int nt = 0; nt < 4; nt++) {
                int nb = wn*32 + nt*8 + g;
                b[nt][0] = Bp[kc*BSTRG + nb];
                b[nt][1] = Bp[(kc+4)*BSTRG + nb];
            }
            #pragma unroll
            for (int mt = 0; mt < 4; mt++)
                #pragma unroll
                for (int nt = 0; nt < 4; nt++) {
                    asm volatile(
                        "mma.sync.aligned.m16n8k8.row.col.f32.tf32.tf32.f32 "
                        "{%0,%1,%2,%3}, {%4,%5,%6,%7}, {%8,%9}, {%0,%1,%2,%3};\n"
                        : "+f"(acc[mt][nt][0]), "+f"(acc[mt][nt][1]),
                          "+f"(acc[mt][nt][2]), "+f"(acc[mt][nt][3])
                        : "r"(a[mt].x), "r"(a[mt].y), "r"(a[mt].z), "r"(a[mt].w),
                          "r"(b[nt][0]), "r"(b[nt][1]));
                }
        }
        if (kt + 2 < ntile) { ISSUE(kt + 2, (kt + 2) % 3); }
        else asm volatile("cp.async.commit_group;\n");
    }
#undef ISSUE

    // ---- epilogue ----
    #pragma unroll
    for (int mt = 0; mt < 4; mt++) {
        #pragma unroll
        for (int half = 0; half < 2; half++) {
            int rr = m0 + wm*64 + mt*16 + g + half*8;
            if (rr >= M) continue;
            const float* srcrow = nullptr;
            const float* grow   = nullptr;
            if (EPI == 1) {
                int b, gcol; long off;
                if (rr < RMAIN) {
                    b = rr / SEQ; int s = rr - b*SEQ;
                    if (s < TXT) { gcol = 5; off = ((long)b*TXT + s)*DIMM; srcrow = ep_e + off; }
                    else         { gcol = 2; off = ((long)b*IMGL + (s - TXT))*DIMM; srcrow = ep_h + off; }
                } else {
                    int qq = rr - RMAIN; b = qq / NCPT; gcol = 5;
                    srcrow = ep_c + (long)qq*DIMM;
                }
                grow = g_s1 + b*6*DIMM + gcol*DIMM;
            }
            #pragma unroll
            for (int nt = 0; nt < 4; nt++) {
                int c0 = n0 + wn*32 + nt*8 + 2*c;
                if (c0 >= N) continue;
                float v0 = acc[mt][nt][half*2 + 0];
                float v1 = acc[mt][nt][half*2 + 1];
                if (bias) { v0 += bias[c0]; v1 += bias[c0+1]; }
                if (ACT == 1) {
                    float u = v0;
                    v0 = 0.5f*u*(1.f + tanhf(0.79788456080286535588f*(u + 0.044715f*u*u*u)));
                    u = v1;
                    v1 = 0.5f*u*(1.f + tanhf(0.79788456080286535588f*(u + 0.044715f*u*u*u)));
                }
                if (ROUND) { v0 = rndf(v0); v1 = rndf(v1); }
                if (EPI == 0) {
                    *(float2*)&C[(long)rr*ldc + c0] = make_float2(v0, v1);
                } else {
                    float2 sv = *(const float2*)&srcrow[c0];
                    float2 gv = *(const float2*)&grow[c0];
                    *(float2*)&g_res[(size_t)rr*DIMM + c0] =
                        make_float2(sv.x + gv.x*v0, sv.y + gv.y*v1);
                }
            }
        }
    }
}

// ---------------- split-K FF2 reduce (4 partials) + resid2 -> final outputs ----------------
__global__ void k_ff2red(float* __restrict__ out, const float* __restrict__ bias)
{
    int r = blockIdx.x, t = threadIdx.x;
    float* dst; int b, gcol;
    if (r < RMAIN) {
        b = r / SEQ; int s = r - b*SEQ;
        if (s < TXT) { dst = out + OE + ((size_t)b*TXT + s)*DIMM; gcol = 5; }
        else         { dst = out + ((size_t)b*IMGL + (s - TXT))*DIMM; gcol = 2; }
    } else {
        int qq = r - RMAIN; b = qq / NCPT;
        dst = out + OC + (size_t)qq*DIMM; gcol = 5;
    }
    const float* g = g_s2 + b*6*DIMM + gcol*DIMM;
    #pragma unroll
    for (int i = 0; i < 4; i++) {
        int j = t + i*256;
        float v = (g_part[(size_t)r*DIMM + j]
                +  g_part[(size_t)(RTOT + r)*DIMM + j])
                + (g_part[(size_t)(2*RTOT + r)*DIMM + j]
                +  g_part[(size_t)(3*RTOT + r)*DIMM + j]) + bias[j];
        dst[j] = g_res[(size_t)r*DIMM + j] + g[j]*v;
    }
}

// ---------------- fused flash attention over g_qkv (stride 3072) ----------------
#define KSTR 68
#define VSTR 65
#define PSTR 68
#define FLASH_SMEM ((64*KSTR + 64*VSTR + 8*16*PSTR)*4)

__global__ void __launch_bounds__(256, 2)
k_flash(const float* __restrict__ qkv, float* __restrict__ og)
{
    extern __shared__ __align__(16) unsigned fsm[];
    unsigned* Ks = fsm;
    unsigned* Vs = Ks + 64*KSTR;
    unsigned* Ps = Vs + 64*VSTR;

    const float* qg = qkv;
    const float* kg = qkv + 1024;
    const float* vg = qkv + 2048;

    int b = blockIdx.y >> 4, h = blockIdx.y & 15;
    int tid = threadIdx.x, lane = tid & 31, w = tid >> 5;
    int g = lane >> 2, c = lane & 3;
    int r0 = blockIdx.x*128 + w*16 + g;
    int r1 = r0 + 8;
    bool v0 = r0 < SEQ, v1 = r1 < SEQ;

    unsigned qf[8][4];
    {
        const float* q0 = qg + (size_t)(b*SEQ + (v0 ? r0 : 0))*QKVS + h*HD;
        const float* q1 = qg + (size_t)(b*SEQ + (v1 ? r1 : 0))*QKVS + h*HD;
        #pragma unroll
        for (int ks = 0; ks < 8; ks++) {
            qf[ks][0] = v0 ? f2tf32(q0[ks*8 + c])     : 0u;
            qf[ks][1] = v1 ? f2tf32(q1[ks*8 + c])     : 0u;
            qf[ks][2] = v0 ? f2tf32(q0[ks*8 + c + 4]) : 0u;
            qf[ks][3] = v1 ? f2tf32(q1[ks*8 + c + 4]) : 0u;
        }
    }

    float mr0 = -1e30f, mr1 = -1e30f;
    float lr0 = 0.f, lr1 = 0.f;
    float O[8][4];
    #pragma unroll
    for (int i = 0; i < 8; i++)
        #pragma unroll
        for (int j = 0; j < 4; j++) O[i][j] = 0.f;

    int kk = tid & 63;
    int dg = (tid >> 6) * 16;
    unsigned* Pw = Ps + w*16*PSTR;

    const int NTILES = (SEQ + 63) / 64;
    for (int t = 0; t < NTILES; t++) {
        __syncthreads();
        {
            int j = t*64 + kk;
            bool jv = j < SEQ;
            const float* kp = kg + (size_t)(b*SEQ + (jv ? j : 0))*QKVS + h*HD + dg;
            const float* vp = vg + (size_t)(b*SEQ + (jv ? j : 0))*QKVS + h*HD + dg;
            #pragma unroll
            for (int i = 0; i < 4; i++) {
                float4 k4 = jv ? *(const float4*)(kp + i*4) : make_float4(0,0,0,0);
                float4 w4 = jv ? *(const float4*)(vp + i*4) : make_float4(0,0,0,0);
                int d = dg + i*4;
                Ks[(d+0)*KSTR + kk] = f2tf32(k4.x);
                Ks[(d+1)*KSTR + kk] = f2tf32(k4.y);
                Ks[(d+2)*KSTR + kk] = f2tf32(k4.z);
                Ks[(d+3)*KSTR + kk] = f2tf32(k4.w);
                Vs[kk*VSTR + d+0] = f2tf32(w4.x);
                Vs[kk*VSTR + d+1] = f2tf32(w4.y);
                Vs[kk*VSTR + d+2] = f2tf32(w4.z);
                Vs[kk*VSTR + d+3] = f2tf32(w4.w);
            }
        }
        __syncthreads();

        float s[8][4];
        #pragma unroll
        for (int i = 0; i < 8; i++)
            #pragma unroll
            for (int j = 0; j < 4; j++) s[i][j] = 0.f;
        #pragma unroll
        for (int ks = 0; ks < 8; ks++) {
            int kc = ks*8 + c;
            #pragma unroll
            for (int nt = 0; nt < 8; nt++) {
                unsigned b0 = Ks[kc*KSTR + nt*8 + g];
                unsigned b1 = Ks[(kc+4)*KSTR + nt*8 + g];
                asm volatile(
                    "mma.sync.aligned.m16n8k8.row.col.f32.tf32.tf32.f32 "
                    "{%0,%1,%2,%3}, {%4,%5,%6,%7}, {%8,%9}, {%0,%1,%2,%3};\n"
                    : "+f"(s[nt][0]), "+f"(s[nt][1]), "+f"(s[nt][2]), "+f"(s[nt][3])
                    : "r"(qf[ks][0]), "r"(qf[ks][1]), "r"(qf[ks][2]), "r"(qf[ks][3]),
                      "r"(b0), "r"(b1));
            }
        }

        int jb = t*64 + 2*c;
        #pragma unroll
        for (int nt = 0; nt < 8; nt++) {
            int j0 = jb + nt*8, j1 = j0 + 1;
            s[nt][0] = (j0 < SEQ) ? s[nt][0]*0.125f : -1e30f;
            s[nt][1] = (j1 < SEQ) ? s[nt][1]*0.125f : -1e30f;
            s[nt][2] = (j0 < SEQ) ? s[nt][2]*0.125f : -1e30f;
            s[nt][3] = (j1 < SEQ) ? s[nt][3]*0.125f : -1e30f;
        }
        float mx0 = -1e30f, mx1 = -1e30f;
        #pragma unroll
        for (int nt = 0; nt < 8; nt++) {
            mx0 = fmaxf(mx0, fmaxf(s[nt][0], s[nt][1]));
            mx1 = fmaxf(mx1, fmaxf(s[nt][2], s[nt][3]));
        }
        mx0 = fmaxf(mx0, __shfl_xor_sync(0xffffffffu, mx0, 1));
        mx0 = fmaxf(mx0, __shfl_xor_sync(0xffffffffu, mx0, 2));
        mx1 = fmaxf(mx1, __shfl_xor_sync(0xffffffffu, mx1, 1));
        mx1 = fmaxf(mx1, __shfl_xor_sync(0xffffffffu, mx1, 2));
        float nm0 = fmaxf(mr0, mx0), nm1 = fmaxf(mr1, mx1);
        float sc0 = __expf(mr0 - nm0), sc1 = __expf(mr1 - nm1);
        float rs0 = 0.f, rs1 = 0.f;
        #pragma unroll
        for (int nt = 0; nt < 8; nt++) {
            float p0 = __expf(s[nt][0] - nm0);
            float p1 = __expf(s[nt][1] - nm0);
            float p2 = __expf(s[nt][2] - nm1);
            float p3 = __expf(s[nt][3] - nm1);
            rs0 += p0 + p1; rs1 += p2 + p3;
            int col = nt*8 + 2*c;
            *(uint2*)&Pw[g*PSTR + col]     = make_uint2(f2tf32(p0), f2tf32(p1));
            *(uint2*)&Pw[(g+8)*PSTR + col] = make_uint2(f2tf32(p2), f2tf32(p3));
        }
        rs0 += __shfl_xor_sync(0xffffffffu, rs0, 1);
        rs0 += __shfl_xor_sync(0xffffffffu, rs0, 2);
        rs1 += __shfl_xor_sync(0xffffffffu, rs1, 1);
        rs1 += __shfl_xor_sync(0xffffffffu, rs1, 2);
        lr0 = lr0*sc0 + rs0;
        lr1 = lr1*sc1 + rs1;
        mr0 = nm0; mr1 = nm1;
        #pragma unroll
        for (int nt = 0; nt < 8; nt++) {
            O[nt][0] *= sc0; O[nt][1] *= sc0;
            O[nt][2] *= sc1; O[nt][3] *= sc1;
        }
        __syncwarp();

        #pragma unroll
        for (int ks = 0; ks < 8; ks++) {
            int kc = ks*8 + c;
            unsigned a0 = Pw[g*PSTR + kc];
            unsigned a1 = Pw[(g+8)*PSTR + kc];
            unsigned a2 = Pw[g*PSTR + kc + 4];
            unsigned a3 = Pw[(g+8)*PSTR + kc + 4];
            #pragma unroll
            for (int nt = 0; nt < 8; nt++) {
                unsigned b0 = Vs[kc*VSTR + nt*8 + g];
                unsigned b1 = Vs[(kc+4)*VSTR + nt*8 + g];
                asm volatile(
                    "mma.sync.aligned.m16n8k8.row.col.f32.tf32.tf32.f32 "
                    "{%0,%1,%2,%3}, {%4,%5,%6,%7}, {%8,%9}, {%0,%1,%2,%3};\n"
                    : "+f"(O[nt][0]), "+f"(O[nt][1]), "+f"(O[nt][2]), "+f"(O[nt][3])
                    : "r"(a0), "r"(a1), "r"(a2), "r"(a3),
                      "r"(b0), "r"(b1));
            }
        }
        __syncwarp();
    }

    float i0 = 1.f/lr0, i1 = 1.f/lr1;
    if (v0) {
        float* op = og + (size_t)(b*SEQ + r0)*DIMM + h*HD;
        #pragma unroll
        for (int nt = 0; nt < 8; nt++)
            *(float2*)&op[nt*8 + 2*c] = make_float2(O[nt][0]*i0, O[nt][1]*i0);
    }
    if (v1) {
        float* op = og + (size_t)(b*SEQ + r1)*DIMM + h*HD;
        #pragma unroll
        for (int nt = 0; nt < 8; nt++)
            *(float2*)&op[nt*8 + 2*c] = make_float2(O[nt][2]*i1, O[nt][3]*i1);
    }
}

// ---------------- fused per-head LN (+RoPE) for q AND k in one launch ----------------
__global__ void k_headln2(float* __restrict__ x,
                          const float* __restrict__ nqw, const float* __restrict__ nqb,
                          const float* __restrict__ nkw, const float* __restrict__ nkb,
                          const float* __restrict__ rc, const float* __restrict__ rs)
{
    int wg = blockIdx.x * 8 + (threadIdx.x >> 5);
    if (wg >= 2*RTOT*HEADS) return;
    int lane = threadIdx.x & 31;
    int kind = (wg >= RTOT*HEADS) ? 1 : 0;      // 0 = q, 1 = k
    int w = kind ? (wg - RTOT*HEADS) : wg;
    int r = w >> 4, h = w & 15;
    const float* nw = kind ? nkw : nqw;
    const float* nb = kind ? nkb : nqb;
    float* p = x + (size_t)r*QKVS + kind*1024 + h*HD;
    float v0 = p[lane], v1 = p[lane + 32];
    float s = v0 + v1;
    #pragma unroll
    for (int o = 16; o; o >>= 1) s += __shfl_xor_sync(0xffffffffu, s, o);
    float mu = s * (1.f/64.f);
    float d0 = v0 - mu, d1 = v1 - mu;
    float qv = d0*d0 + d1*d1;
    #pragma unroll
    for (int o = 16; o; o >>= 1) qv += __shfl_xor_sync(0xffffffffu, qv, o);
    float rstd = rsqrtf(qv*(1.f/64.f) + 1e-6f);
    float y0 = d0*rstd*nw[lane]    + nb[lane];
    float y1 = d1*rstd*nw[lane+32] + nb[lane+32];
    if (r < RMAIN) {
        int sidx = r % SEQ;
        if (sidx >= TXT) {
            int pos = sidx - TXT;
            const float* c  = rc + (size_t)pos*HD;
            const float* sn = rs + (size_t)pos*HD;
            float p0 = __shfl_xor_sync(0xffffffffu, y0, 1);
            float p1 = __shfl_xor_sync(0xffffffffu, y1, 1);
            float r0 = (lane & 1) ? p0 : -p0;
            float r1 = (lane & 1) ? p1 : -p1;
            y0 = y0*c[lane]    + r0*sn[lane];
            y1 = y1*c[lane+32] + r1*sn[lane+32];
        }
    }
    p[lane] = y0; p[lane+32] = y1;
}

// ---------------- concept attention: scores+softmax per (b,h,c) ----------------
__global__ void k_cscore(const float* __restrict__ qkv)
{
    int bid = blockIdx.x;
    int b = bid >> 7, h = (bid >> 3) & 15, c = bid & 7;
    int t = threadIdx.x;
    __shared__ float qs[HD];
    __shared__ float red[32];
    const float* qrow = qkv + (size_t)(RMAIN + b*NCPT + c)*QKVS + h*HD;
    if (t < HD) qs[t] = qrow[t];
    __syncthreads();
    float v[7];
    float m = -1e30f;
    #pragma unroll
    for (int i = 0; i < 7; i++) {
        int j = t + i*256;
        if (j < CKEYS) {
            const float* krow = (j < NCPT)
                ? qkv + (size_t)(RMAIN + b*NCPT + j)*QKVS + 1024 + h*HD
                : qkv + (size_t)(b*SEQ + TXT + (j - NCPT))*QKVS + 1024 + h*HD;
            float a = 0.f;
            for (int d = 0; d < HD; d++) a += qs[d]*krow[d];
            v[i] = a*0.125f;
        } else v[i] = -1e30f;
        m = fmaxf(m, v[i]);
    }
    m = blockReduceMax(m, red);
    float s = 0.f;
    #pragma unroll
    for (int i = 0; i < 7; i++) {
        int j = t + i*256;
        v[i] = (j < CKEYS) ? __expf(v[i]-m) : 0.f;
        s += v[i];
    }
    s = blockReduceSum(s, red);
    float inv = 1.f/s;
    float* out = g_cs + ((size_t)(b*HEADS + h)*NCPT + c)*CKEYS;
    #pragma unroll
    for (int i = 0; i < 7; i++) {
        int j = t + i*256;
        if (j < CKEYS) out[j] = v[i]*inv;
    }
}

__global__ void k_cpv(const float* __restrict__ qkv)
{
    int bid = blockIdx.x; int b = bid >> 7, h = (bid >> 3) & 15, c = bid & 7;
    int t = threadIdx.x;
    int d  = t & 63;
    int jg = t >> 6;
    const float* p = g_cs + ((size_t)(b*HEADS + h)*NCPT + c)*CKEYS;
    float acc = 0.f;
    for (int j = jg; j < CKEYS; j += 4) {
        const float* vrow = (j < NCPT)
            ? qkv + (size_t)(RMAIN + b*NCPT + j)*QKVS + 2048 + h*HD
            : qkv + (size_t)(b*SEQ + TXT + (j - NCPT))*QKVS + 2048 + h*HD;
        acc += p[j]*vrow[d];
    }
    __shared__ float part[4][64];
    part[jg][d] = acc;
    __syncthreads();
    if (t < 64)
        g_attn[(size_t)(RMAIN + b*NCPT + c)*DIMM + h*HD + t] =
            part[0][t] + part[1][t] + part[2][t] + part[3][t];
}

// ---------------- head score (batch 1), top-k ----------------
__global__ void k_headscore()
{
    int h = blockIdx.x, t = threadIdx.x;
    float s1 = 0.f, s2 = 0.f;
    for (int p = t; p < IMGL; p += 256) {
        const float* row = g_attn + (size_t)(SEQ + TXT + p)*DIMM + h*HD;
        float m = 0.f;
        for (int d = 0; d < HD; d++) m += row[d];
        m *= (1.f/64.f);
        s1 += m; s2 += m*m;
    }
    __shared__ float red[32];
    s1 = blockReduceSum(s1, red);
    s2 = blockReduceSum(s2, red);
    if (t == 0) {
        float mu = s1/IMGL;
        g_hscore[h] = sqrtf(fmaxf(s2/IMGL - mu*mu, 0.f));
    }
}

__global__ void k_topk()
{
    if (threadIdx.x) return;
    bool used[HEADS] = {};
    for (int i = 0; i < 4; i++) {
        int bi = -1; float bv = -1e30f;
        for (int hh = 0; hh < HEADS; hh++)
            if (!used[hh] && g_hscore[hh] > bv) { bv = g_hscore[hh]; bi = hh; }
        used[bi] = true; g_selhead[i] = bi;
    }
}

// ---------------- sim argmax over patches per (h, concept, frame) ----------------
__global__ void k_simargmax(const float* __restrict__ qkv)
{
    int h = blockIdx.x, tc = blockIdx.y, f = blockIdx.z;
    int t = threadIdx.x;
    __shared__ float ks[HD];
    if (t < HD) ks[t] = qkv[(size_t)(RMAIN + NCPT + tc)*QKVS + 1024 + h*HD + t];
    __syncthreads();
    float bv = -1e30f; int bi = 0;
    #pragma unroll
    for (int i = 0; i < 3; i++) {
        int p = t + i*128;
        const float* qrow = qkv + (size_t)(SEQ + TXT + f*PATCHES + p)*QKVS + h*HD;
        float a = 0.f;
        for (int d = 0; d < HD; d++) a += qrow[d]*ks[d];
        if (a > bv) { bv = a; bi = p; }
    }
    __shared__ float sv[128]; __shared__ int si[128];
    sv[t] = bv; si[t] = bi;
    __syncthreads();
    for (int o = 64; o; o >>= 1) {
        if (t < o) {
            if (sv[t+o] > sv[t] || (sv[t+o] == sv[t] && si[t+o] < si[t])) {
                sv[t] = sv[t+o]; si[t] = si[t+o];
            }
        }
        __syncthreads();
    }
    if (t == 0) g_selvis[(h*NCPT + tc)*FRAMES + f] = si[0];
}

// ---------------- imap per (h, f) ----------------
__global__ void k_imap()
{
    int h = blockIdx.x, f = blockIdx.y;
    int t = threadIdx.x;
    __shared__ float sel[NCPT][HD];
    for (int idx = t; idx < NCPT*HD; idx += 384) {
        int tc = idx >> 6, d = idx & 63;
        int sp = g_selvis[(h*NCPT + tc)*FRAMES + f];
        sel[tc][d] = g_attn[(size_t)(SEQ + TXT + f*PATCHES + sp)*DIMM + h*HD + d];
    }
    __syncthreads();
    const float* row = g_attn + (size_t)(SEQ + TXT + f*PATCHES + t)*DIMM + h*HD;
    float a[NCPT] = {};
    for (int d = 0; d < HD; d++) {
        float x = row[d];
        #pragma unroll
        for (int tc = 0; tc < NCPT; tc++) a[tc] += sel[tc][d]*x;
    }
    float mu = 0.f;
    #pragma unroll
    for (int tc = 0; tc < NCPT; tc++) mu += a[tc];
    mu *= (1.f/8.f);
    float var = 0.f;
    #pragma unroll
    for (int tc = 0; tc < NCPT; tc++) { float d_ = a[tc]-mu; var += d_*d_; }
    float sd = sqrtf(var*(1.f/7.f)) + 1e-6f;
    #pragma unroll
    for (int tc = 0; tc < NCPT; tc++)
        g_imap[((size_t)(h*NCPT + tc))*IMGL + f*PATCHES + t] = (a[tc]-mu)/sd;
}

__global__ void k_selfinal(float* __restrict__ out)
{
    int idx = blockIdx.x*256 + threadIdx.x;
    if (idx >= NCPT*IMGL) return;
    int tc = idx / IMGL, p = idx % IMGL;
    float ssum = 0.f;
    for (int i = 0; i < 4; i++)
        ssum += g_imap[((size_t)(g_selhead[i]*NCPT + tc))*IMGL + p];
    out[OSEL + idx] = ssum*0.25f;
    float tot = 0.f;
    for (int h = 0; h < HEADS; h++)
        tot += g_imap[((size_t)(h*NCPT + tc))*IMGL + p];
    out[OIMAP + idx] = tot;
}

// ---------------- cross/concept maps ----------------
__global__ void k_dotmaps(const float* __restrict__ A, const float* __restrict__ Brows,
                          int lda, int ldb, float* __restrict__ out, float scale)
{
    int w = blockIdx.x*8 + (threadIdx.x >> 5);
    if (w >= NCPT*IMGL) return;
    int lane = threadIdx.x & 31;
    int c = w / IMGL, p = w % IMGL;
    const float* a = A     + (size_t)(SEQ + TXT + p)*lda;
    const float* b = Brows + (size_t)(RMAIN + NCPT + c)*ldb;
    float s = 0.f;
    for (int i = lane; i < DIMM; i += 32) s += a[i]*b[i];
    #pragma unroll
    for (int o = 16; o; o >>= 1) s += __shfl_xor_sync(0xffffffffu, s, o);
    if (lane == 0) out[c*IMGL + p] = s*scale;
}

// ---------------- host launcher ----------------
static float* symf(const void* symbol) {
    void* p = nullptr;
    cudaGetSymbolAddress(&p, symbol);
    return (float*)p;
}

extern "C" void kernel_launch(void* const* d_in, const int* in_sizes, int n_in,
                              void* d_out, int out_size)
{
    const float* h_in  = (const float*)d_in[0];
    const float* e_in  = (const float*)d_in[1];
    const float* c_in  = (const float*)d_in[2];
    const float* temb  = (const float*)d_in[3];
    const float* ropec = (const float*)d_in[4];
    const float* ropes = (const float*)d_in[5];
    const float* n1w   = (const float*)d_in[6];
    const float* n1b   = (const float*)d_in[7];
    const float* ln1w  = (const float*)d_in[8];
    const float* ln1b  = (const float*)d_in[9];
    const float* n2w   = (const float*)d_in[10];
    const float* n2b   = (const float*)d_in[11];
    const float* ln2w  = (const float*)d_in[12];
    const float* ln2b  = (const float*)d_in[13];
    const float* wq    = (const float*)d_in[14];
    const float* wk    = (const float*)d_in[15];
    const float* wv    = (const float*)d_in[16];
    const float* nqw   = (const float*)d_in[17];
    const float* nqb   = (const float*)d_in[18];
    const float* nkw   = (const float*)d_in[19];
    const float* nkb   = (const float*)d_in[20];
    const float* wo    = (const float*)d_in[21];
    const float* bo    = (const float*)d_in[22];
    const float* ffw1  = (const float*)d_in[23];
    const float* ffb1  = (const float*)d_in[24];
    const float* ffw2  = (const float*)d_in[25];
    const float* ffb2  = (const float*)d_in[26];
    float* out = (float*)d_out;

    float* px    = symf(g_x);
    float* pqkv  = symf(g_qkv);
    float* pattn = symf(g_attn);
    float* pffh  = symf(g_ffh);
    float* ppart = symf(g_part);
    float* pwqkv = symf(g_wqkv);
    float* pwo   = symf(g_wo);
    float* pw1   = symf(g_w1);
    float* pw2   = symf(g_w2);

    cudaFuncSetAttribute(mma_gemm<0,0,0>, cudaFuncAttributeMaxDynamicSharedMemorySize, SMEM_GEMM);
    cudaFuncSetAttribute(mma_gemm<0,0,1>, cudaFuncAttributeMaxDynamicSharedMemorySize, SMEM_GEMM);
    cudaFuncSetAttribute(mma_gemm<1,1,0>, cudaFuncAttributeMaxDynamicSharedMemorySize, SMEM_GEMM);
    cudaFuncSetAttribute(k_flash, cudaFuncAttributeMaxDynamicSharedMemorySize, FLASH_SMEM);

    static cudaStream_t s1 = nullptr, s2 = nullptr;
    static cudaEvent_t e_prep, e_fork, e_hqk, e_flash, e_cpv, e_sim, e_end1, e_end2;
    if (!s1) {
        cudaStreamCreateWithFlags(&s1, cudaStreamNonBlocking);
        cudaStreamCreateWithFlags(&s2, cudaStreamNonBlocking);
        cudaEventCreateWithFlags(&e_prep,  cudaEventDisableTiming);
        cudaEventCreateWithFlags(&e_fork,  cudaEventDisableTiming);
        cudaEventCreateWithFlags(&e_hqk,   cudaEventDisableTiming);
        cudaEventCreateWithFlags(&e_flash, cudaEventDisableTiming);
        cudaEventCreateWithFlags(&e_cpv,   cudaEventDisableTiming);
        cudaEventCreateWithFlags(&e_sim,   cudaEventDisableTiming);
        cudaEventCreateWithFlags(&e_end1,  cudaEventDisableTiming);
        cudaEventCreateWithFlags(&e_end2,  cudaEventDisableTiming);
    }
    cudaStream_t s0 = 0;

    // fork side streams from s0
    cudaEventRecord(e_fork, s0);
    cudaStreamWaitEvent(s1, e_fork, 0);
    cudaStreamWaitEvent(s2, e_fork, 0);
    k_prep<<<4096, 256, 0, s1>>>(wq, wk, wv, wo, ffw1, ffw2);
    cudaEventRecord(e_prep, s1);

    k_mod<<<dim3(24,2,2), 256, 0, s0>>>(temb, n1w, n1b, n2w, n2b);
    k_ln_mod<<<RTOT, 256, 0, s0>>>(e_in, h_in, c_in, 0, 0, ln1w, ln1b);

    cudaStreamWaitEvent(s0, e_prep, 0);
    mma_gemm<0,0,0><<<dim3(24,28),256,SMEM_GEMM,s0>>>(px, pwqkv, nullptr, pqkv,
                                                      RTOT, QKVS, DIMM, DIMM, QKVS, QKVS,
                                                      nullptr, nullptr, nullptr, 0, 0, 0);

    // fused per-head LN + RoPE for q and k in one launch on s0
    k_headln2<<<14160, 256, 0, s0>>>(pqkv, nqw, nqb, nkw, nkb, ropec, ropes);
    cudaEventRecord(e_hqk, s0);

    // flash attention on s0
    k_flash<<<dim3(14, 32), 256, FLASH_SMEM, s0>>>(pqkv, pattn);
    cudaEventRecord(e_flash, s0);

    // s1: concept attention (needs headln q+k)
    cudaStreamWaitEvent(s1, e_hqk, 0);
    k_cscore<<<256, 256, 0, s1>>>(pqkv);
    k_cpv<<<256, 256, 0, s1>>>(pqkv);
    cudaEventRecord(e_cpv, s1);

    // s2: qk-only maps
    cudaStreamWaitEvent(s2, e_hqk, 0);
    k_simargmax<<<dim3(HEADS, NCPT, FRAMES), 128, 0, s2>>>(pqkv);
    cudaEventRecord(e_sim, s2);
    k_dotmaps<<<1536, 256, 0, s2>>>(pqkv, pqkv + 1024, QKVS, QKVS, out + OXMAP, 1.f/16.f);
    cudaStreamWaitEvent(s2, e_flash, 0);
    cudaStreamWaitEvent(s2, e_cpv, 0);
    k_dotmaps<<<1536, 256, 0, s2>>>(pattn, pattn, DIMM, DIMM, out + OCMAP, 1.f);
    cudaEventRecord(e_end2, s2);

    // s1: attn-dependent maps
    cudaStreamWaitEvent(s1, e_flash, 0);
    k_headscore<<<HEADS, 256, 0, s1>>>();
    k_topk<<<1, 32, 0, s1>>>();
    cudaStreamWaitEvent(s1, e_sim, 0);
    k_imap<<<dim3(HEADS, FRAMES), PATCHES, 0, s1>>>();
    k_selfinal<<<48, 256, 0, s1>>>(out);
    cudaEventRecord(e_end1, s1);

    // Wo projection: unsplit, fused resid1 epilogue -> writes g_res directly
    cudaStreamWaitEvent(s0, e_cpv, 0);
    mma_gemm<0,0,1><<<dim3(8,28),256,SMEM_GEMM,s0>>>(pattn, pwo, bo, out,
                                                     RTOT, DIMM, DIMM, DIMM, DIMM, DIMM,
                                                     e_in, h_in, c_in, 0, 0, 0);

    // LN phase 2, FF1, split-K=4 FF2 partials, reduce + resid2
    k_ln_mod<<<RTOT, 256, 0, s0>>>(e_in, h_in, c_in, 1, 1, ln2w, ln2b);
    mma_gemm<1,1,0><<<dim3(32,28),256,SMEM_GEMM,s0>>>(px, pw1, ffb1, pffh,
                                                      RTOT, FFD, DIMM, DIMM, FFD, FFD,
                                                      nullptr, nullptr, nullptr, 0, 0, 0);
    mma_gemm<0,0,0><<<dim3(8,28,4),256,SMEM_GEMM,s0>>>(pffh, pw2, nullptr, ppart,
                                                       RTOT, DIMM, 1024, FFD, DIMM, DIMM,
                                                       nullptr, nullptr, nullptr,
                                                       1024L, 1024L*DIMM, (long)RTOT*DIMM);
    k_ff2red<<<RTOT, 256, 0, s0>>>(out, ffb2);

    cudaStreamWaitEvent(s0, e_end1, 0);
    cudaStreamWaitEvent(s0, e_end2, 0);
}